// round 8
// baseline (speedup 1.0000x reference)
#include <cuda_runtime.h>
#include <math.h>
#include <stdint.h>

// ---------------------------------------------------------------------------
// Problem constants
// ---------------------------------------------------------------------------
constexpr int BATCH = 256;
constexpr int N0 = 2048;
constexpr int N1 = 4096;
constexpr int N2 = 8192;
constexpr float LAMB = 0.5f;
constexpr int MAX_ITERS = 64;

// ---------------------------------------------------------------------------
// Persistent state + split-K scratch (__device__ globals)
// ---------------------------------------------------------------------------
__device__ float g_v0[BATCH * N0], g_t0[BATCH * N0], g_e0[BATCH * N0];
__device__ float g_v1[BATCH * N1], g_t1[BATCH * N1], g_e1[BATCH * N1];
__device__ float g_e2[BATCH * N2];
__device__ float sP0[2][BATCH * N0];   // e1@W0 partials (UPD0)
__device__ float sP1[4][BATCH * N1];   // e2@W1 partials (UPD1)
__device__ float sQ1[BATCH * N1];      // t0@W0^T (FWD1/ERR1)
__device__ float sQ2[2][BATCH * N2];   // t1@W1^T partials (ERR2)
__device__ double g_loss[MAX_ITERS];

// ---------------------------------------------------------------------------
// PTX helpers (sm_80 baseline; ptxas target is plain sm_103)
// ---------------------------------------------------------------------------
__device__ __forceinline__ uint32_t s2u(const void* p) {
    uint32_t a;
    asm("{ .reg .u64 t; cvta.to.shared.u64 t, %1; cvt.u32.u64 %0, t; }"
        : "=r"(a) : "l"(p));
    return a;
}
__device__ __forceinline__ void cp_async16(uint32_t saddr, const void* gaddr) {
    asm volatile("cp.async.cg.shared.global [%0], [%1], 16;"
                 :: "r"(saddr), "l"(gaddr) : "memory");
}
__device__ __forceinline__ void cp_commit() {
    asm volatile("cp.async.commit_group;" ::: "memory");
}
template <int N>
__device__ __forceinline__ void cp_wait() {
    asm volatile("cp.async.wait_group %0;" :: "n"(N) : "memory");
}
__device__ __forceinline__ void mma_tf32(float* d, const uint32_t* a, const uint32_t* b) {
    asm volatile(
        "mma.sync.aligned.m16n8k8.row.col.f32.tf32.tf32.f32 "
        "{%0,%1,%2,%3}, {%4,%5,%6,%7}, {%8,%9}, {%0,%1,%2,%3};"
        : "+f"(d[0]), "+f"(d[1]), "+f"(d[2]), "+f"(d[3])
        : "r"(a[0]), "r"(a[1]), "r"(a[2]), "r"(a[3]), "r"(b[0]), "r"(b[1]));
}
__device__ __forceinline__ void split_tf32(float x, uint32_t& h, uint32_t& l) {
    uint32_t hu;
    asm("cvt.rna.tf32.f32 %0, %1;" : "=r"(hu) : "f"(x));
    float hf = __uint_as_float(hu);
    uint32_t lu;
    asm("cvt.rna.tf32.f32 %0, %1;" : "=r"(lu) : "f"(x - hf));
    h = hu;
    l = lu;
}

// ---------------------------------------------------------------------------
// init
// ---------------------------------------------------------------------------
__global__ void init_state_k(const float* __restrict__ memory) {
    int i0 = blockIdx.x * blockDim.x + threadIdx.x;
    int stride = gridDim.x * blockDim.x;
    if (i0 < MAX_ITERS) g_loss[i0] = 0.0;
    for (int i = i0; i < BATCH * N0; i += stride) {
        float m = memory[i & (N0 - 1)];
        g_v0[i] = m;
        g_t0[i] = tanhf(m);
        g_e0[i] = 0.0f;
    }
    for (int i = i0; i < BATCH * N1; i += stride) g_e1[i] = 0.0f;
}

// ---------------------------------------------------------------------------
// Split-K GEMM (pure partial writer), 3xTF32 on-the-fly (fp32-accurate)
// CTA tile 64m x 128n, 2 warps (each 64x64), KC=32, 2-stage cp.async,
// KPART=2048. 4 CTAs/SM.
// Modes: 0: t0@W0^T -> sQ1     (BT, K=N0)
//        1: t1@W1^T -> sQ2[p]  (BT, K=N1, 2 parts)
//        2: e1@W0   -> sP0[p]  (NN, K=N1, 2 parts)
//        3: e2@W1   -> sP1[p]  (NN, K=N2, 4 parts)
// ---------------------------------------------------------------------------
constexpr int KC = 32, STG = 2, KPART = 2048;
constexpr int LDA = 36;    // A smem stride (rows = m)
constexpr int LDBT = 36;   // B smem stride, BT (rows = n, 128 rows)
constexpr int LDBN = 136;  // B smem stride, NN (rows = k, 32 rows); 136%32=8
constexpr int ASZ = 64 * LDA;                  // 2304 floats
constexpr int BSZ = 128 * LDBT;                // 4608 floats (>= 32*136=4352)
constexpr int STAGE_F = ASZ + BSZ;             // 6912 floats (27648 B)
constexpr int SMEM_BYTES = STG * STAGE_F * 4;  // 55296 B

template <int MODE>
__device__ __forceinline__ void gemm_body(int bx, int by, int part,
                                          const float* __restrict__ Wg) {
    constexpr bool BT = (MODE == 0 || MODE == 1);
    constexpr int NF = (MODE == 0) ? N1 : (MODE == 1) ? N2 : (MODE == 2) ? N0 : N1;
    constexpr int KF = (MODE == 0) ? N0 : (MODE == 1) ? N1 : (MODE == 2) ? N1 : N2;
    constexpr int NCH = KPART / KC;  // 64

    const float* __restrict__ Ag =
        (MODE == 0) ? g_t0 : (MODE == 1) ? g_t1 : (MODE == 2) ? g_e1 : g_e2;
    float* __restrict__ dst =
        (MODE == 0) ? sQ1 : (MODE == 1) ? sQ2[part]
        : (MODE == 2) ? sP0[part] : sP1[part];

    extern __shared__ float sm[];
    const uint32_t sb = s2u(sm);
    const int tid = threadIdx.x;
    const int wn = tid >> 5;    // warp n index (0..1)
    const int lane = tid & 31;
    const int tq = lane >> 2;   // 0..7
    const int tr = lane & 3;    // 0..3
    const int bm = by * 64;
    const int bn = bx * 128;

    auto load_chunk = [&](int c, int st) {
        const int kt = part * KPART + c * KC;
        uint32_t sA = sb + (uint32_t)st * STAGE_F * 4;
        // A: 64 rows x 32 k -> 512 float4, 8 per thread
#pragma unroll
        for (int i = 0; i < 8; i++) {
            int f = tid + i * 64;
            int row = f >> 3, seg = f & 7;
            cp_async16(sA + row * (LDA * 4) + seg * 16,
                       Ag + (size_t)(bm + row) * KF + kt + seg * 4);
        }
        uint32_t sB = sA + ASZ * 4;
        if (BT) {
            // B: 128 n-rows x 32 k -> 1024 float4, 16 per thread
#pragma unroll
            for (int i = 0; i < 16; i++) {
                int f = tid + i * 64;
                int row = f >> 3, seg = f & 7;
                cp_async16(sB + row * (LDBT * 4) + seg * 16,
                           Wg + (size_t)(bn + row) * KF + kt + seg * 4);
            }
        } else {
            // B: 32 k-rows x 128 n -> 1024 float4, 16 per thread
#pragma unroll
            for (int i = 0; i < 16; i++) {
                int f = tid + i * 64;
                int row = f >> 5, seg = f & 31;
                cp_async16(sB + row * (LDBN * 4) + seg * 16,
                           Wg + (size_t)(kt + row) * NF + bn + seg * 4);
            }
        }
        cp_commit();
    };

    float d[4][8][4];
#pragma unroll
    for (int mi = 0; mi < 4; mi++)
#pragma unroll
        for (int ni = 0; ni < 8; ni++)
#pragma unroll
            for (int r = 0; r < 4; r++) d[mi][ni][r] = 0.0f;

    load_chunk(0, 0);

    for (int c = 0; c < NCH; c++) {
        cp_wait<0>();
        __syncthreads();
        int nc = c + 1;
        if (nc < NCH) load_chunk(nc, nc & 1);

        const float* As = sm + (c & 1) * STAGE_F;
        const float* Bs = As + ASZ;
#pragma unroll
        for (int step = 0; step < KC / 8; step++) {
            const int kk = step * 8;
            uint32_t aH[4][4], aL[4][4];
#pragma unroll
            for (int mi = 0; mi < 4; mi++) {
                int r = mi * 16 + tq;
                split_tf32(As[r * LDA + kk + tr],           aH[mi][0], aL[mi][0]);
                split_tf32(As[(r + 8) * LDA + kk + tr],     aH[mi][1], aL[mi][1]);
                split_tf32(As[r * LDA + kk + tr + 4],       aH[mi][2], aL[mi][2]);
                split_tf32(As[(r + 8) * LDA + kk + tr + 4], aH[mi][3], aL[mi][3]);
            }
            uint32_t bH[8][2], bL[8][2];
#pragma unroll
            for (int ni = 0; ni < 8; ni++) {
                int n = wn * 64 + ni * 8 + tq;
                float b0, b1;
                if (BT) {
                    b0 = Bs[n * LDBT + kk + tr];
                    b1 = Bs[n * LDBT + kk + tr + 4];
                } else {
                    b0 = Bs[(kk + tr) * LDBN + n];
                    b1 = Bs[(kk + tr + 4) * LDBN + n];
                }
                split_tf32(b0, bH[ni][0], bL[ni][0]);
                split_tf32(b1, bH[ni][1], bL[ni][1]);
            }
#pragma unroll
            for (int mi = 0; mi < 4; mi++)
#pragma unroll
                for (int ni = 0; ni < 8; ni++) {
                    mma_tf32(d[mi][ni], aH[mi], bH[ni]);
                    mma_tf32(d[mi][ni], aH[mi], bL[ni]);
                    mma_tf32(d[mi][ni], aL[mi], bH[ni]);
                }
        }
        __syncthreads();
    }

    // write partial tile (plain stores; deterministic)
#pragma unroll
    for (int mi = 0; mi < 4; mi++)
#pragma unroll
        for (int ni = 0; ni < 8; ni++)
#pragma unroll
            for (int hf = 0; hf < 2; hf++) {
                int row = bm + mi * 16 + tq + hf * 8;
                int col = bn + wn * 64 + ni * 8 + tr * 2;
                *(float2*)&dst[(size_t)row * NF + col] =
                    make_float2(d[mi][ni][hf * 2], d[mi][ni][hf * 2 + 1]);
            }
}

// ---------------------------------------------------------------------------
// Fused phase GEMM kernels (1-D grid of uniform-duration CTAs)
// Tiles (64m x 128n, m tiles = 4):
//   mode2: 2 parts x (16 n x 4 m) = 128   mode3: 4 x (32 x 4) = 512 -> upd 640
//   mode0: 32 x 4 = 128                   mode1: 2 x (64 x 4) = 512 -> err 640
// ---------------------------------------------------------------------------
__global__ __launch_bounds__(64, 4)
void upd_gemm(const float* __restrict__ W0, const float* __restrict__ W1) {
    int b = blockIdx.x;
    if (b < 128) {
        int part = b >> 6, t = b & 63;
        gemm_body<2>(t & 15, t >> 4, part, W0);
    } else {
        int b2 = b - 128;
        int part = b2 >> 7, t = b2 & 127;
        gemm_body<3>(t & 31, t >> 5, part, W1);
    }
}
__global__ __launch_bounds__(64, 4)
void err_gemm(const float* __restrict__ W0, const float* __restrict__ W1, int boff) {
    int b = blockIdx.x + boff;
    if (b < 128) {
        gemm_body<0>(b & 31, b >> 5, 0, W0);
    } else {
        int b2 = b - 128;
        int part = b2 >> 8, t = b2 & 255;
        gemm_body<1>(t & 63, t >> 6, part, W1);
    }
}

// ---------------------------------------------------------------------------
// Epilogue kernels (elementwise, float4)
// ---------------------------------------------------------------------------
__device__ __forceinline__ void block_loss(float lsum, int loss_idx) {
    __shared__ float wred[8];
    int tid = threadIdx.x;
#pragma unroll
    for (int o = 16; o > 0; o >>= 1)
        lsum += __shfl_down_sync(0xffffffffu, lsum, o);
    if ((tid & 31) == 0) wred[tid >> 5] = lsum;
    __syncthreads();
    if (tid == 0 && loss_idx >= 0) {
        float s = 0.f;
#pragma unroll
        for (int w = 0; w < 8; w++) s += wred[w];
        atomicAdd(&g_loss[loss_idx], (double)s);
    }
}

// grid 1536 x 256 : v0 update (131072 f4) then v1 update (262144 f4)
__global__ __launch_bounds__(256)
void upd_epi(const float* __restrict__ memory, const float* __restrict__ lr_p,
             int loss_idx) {
    int i = blockIdx.x * blockDim.x + threadIdx.x;
    float lr = *lr_p;
    float lsum = 0.f;
    if (i < BATCH * N0 / 4) {
        float4 p0 = ((const float4*)sP0[0])[i];
        float4 p1 = ((const float4*)sP0[1])[i];
        float4 v4 = ((const float4*)g_v0)[i];
        float4 e4 = ((const float4*)g_e0)[i];
        float4 t4 = ((const float4*)g_t0)[i];
        float4 m4 = *(const float4*)&memory[(i * 4) & (N0 - 1)];
        float* p = &p0.x; float* pl = &p1.x;
        float* v = &v4.x; float* e = &e4.x; float* t = &t4.x; float* m = &m4.x;
        float4 nv4, nt4, ne4;
        float* nv = &nv4.x; float* nt = &nt4.x; float* ne = &ne4.x;
#pragma unroll
        for (int c = 0; c < 4; c++) {
            float g = p[c] + pl[c];
            float sg = (v[c] > 0.f) ? 1.f : ((v[c] < 0.f) ? -1.f : 0.f);
            float x = fmaxf(v[c] + lr * (-e[c] - LAMB * sg + (1.f - t[c] * t[c]) * g), 0.f);
            nv[c] = x;
            nt[c] = tanhf(x);
            float er = x - m[c];
            ne[c] = er;
            lsum += er * er;
        }
        ((float4*)g_v0)[i] = nv4;
        ((float4*)g_t0)[i] = nt4;
        ((float4*)g_e0)[i] = ne4;
    } else {
        int j = i - BATCH * N0 / 4;
        float4 p0 = ((const float4*)sP1[0])[j];
        float4 p1 = ((const float4*)sP1[1])[j];
        float4 p2 = ((const float4*)sP1[2])[j];
        float4 p3 = ((const float4*)sP1[3])[j];
        float4 v4 = ((const float4*)g_v1)[j];
        float4 e4 = ((const float4*)g_e1)[j];
        float4 t4 = ((const float4*)g_t1)[j];
        float* a0 = &p0.x; float* a1 = &p1.x; float* a2 = &p2.x; float* a3 = &p3.x;
        float* v = &v4.x; float* e = &e4.x; float* t = &t4.x;
        float4 nv4, nt4;
        float* nv = &nv4.x; float* nt = &nt4.x;
#pragma unroll
        for (int c = 0; c < 4; c++) {
            float g = (a0[c] + a1[c]) + (a2[c] + a3[c]);
            float x = fmaxf(v[c] + lr * (-e[c] + (1.f - t[c] * t[c]) * g), 0.f);
            nv[c] = x;
            nt[c] = tanhf(x);
        }
        ((float4*)g_v1)[j] = nv4;
        ((float4*)g_t1)[j] = nt4;
    }
    block_loss(lsum, loss_idx);
}

// grid 3072 x 256 : e1 (262144 f4, skipped when mode=1) then e2 (524288 f4)
__global__ __launch_bounds__(256)
void err_epi(const float* __restrict__ inp, int loss_idx, int mode) {
    int i = blockIdx.x * blockDim.x + threadIdx.x;
    float lsum = 0.f;
    if (i < BATCH * N1 / 4) {
        if (mode == 0) {
            float4 q = ((const float4*)sQ1)[i];
            float4 v = ((const float4*)g_v1)[i];
            float4 e = make_float4(v.x - q.x, v.y - q.y, v.z - q.z, v.w - q.w);
            ((float4*)g_e1)[i] = e;
            lsum = e.x * e.x + e.y * e.y + e.z * e.z + e.w * e.w;
        }
    } else {
        int j = i - BATCH * N1 / 4;
        float4 q0 = ((const float4*)sQ2[0])[j];
        float4 q1 = ((const float4*)sQ2[1])[j];
        float4 x = ((const float4*)inp)[j];
        float4 e = make_float4(x.x - (q0.x + q1.x), x.y - (q0.y + q1.y),
                               x.z - (q0.z + q1.z), x.w - (q0.w + q1.w));
        ((float4*)g_e2)[j] = e;
        lsum = e.x * e.x + e.y * e.y + e.z * e.z + e.w * e.w;
    }
    block_loss(lsum, loss_idx);
}

// grid 1024 x 256 : v1 = q1, t1 = tanh(q1)
__global__ __launch_bounds__(256)
void fwd_epi() {
    int i = blockIdx.x * blockDim.x + threadIdx.x;
    float4 q = ((const float4*)sQ1)[i];
    ((float4*)g_v1)[i] = q;
    float4 t = make_float4(tanhf(q.x), tanhf(q.y), tanhf(q.z), tanhf(q.w));
    ((float4*)g_t1)[i] = t;
}

__global__ void finalize_kernel(float* __restrict__ out, int n) {
    int i = threadIdx.x;
    if (i < n) out[i] = (float)(g_loss[i] * (100.0 / (double)BATCH));
}

// ---------------------------------------------------------------------------
// Launch (graph-capturable)
// Inputs: batch_inp, W0, W1, memory, n_iters, inf_lr
// ---------------------------------------------------------------------------
extern "C" void kernel_launch(void* const* d_in, const int* in_sizes, int n_in,
                              void* d_out, int out_size) {
    const float* batch_inp = (const float*)d_in[0];
    const float* W0 = (const float*)d_in[1];
    const float* W1 = (const float*)d_in[2];
    const float* memory = (const float*)d_in[3];
    const float* inf_lr = (const float*)d_in[5];

    int n_iters = out_size;
    if (n_iters > MAX_ITERS) n_iters = MAX_ITERS;

    cudaFuncSetAttribute(upd_gemm, cudaFuncAttributeMaxDynamicSharedMemorySize, SMEM_BYTES);
    cudaFuncSetAttribute(err_gemm, cudaFuncAttributeMaxDynamicSharedMemorySize, SMEM_BYTES);

    init_state_k<<<512, 256>>>(memory);

    // init: v1 = t0@W0^T, t1 = tanh(v1); e1 stays exactly 0; e2 = inp - t1@W1^T
    err_gemm<<<128, 64, SMEM_BYTES>>>(W0, W1, 0);     // mode 0 -> sQ1
    fwd_epi<<<1024, 256>>>();
    err_gemm<<<512, 64, SMEM_BYTES>>>(W0, W1, 128);   // mode 1 -> sQ2
    err_epi<<<3072, 256>>>(batch_inp, -1, 1);         // e2 only, no loss

    for (int it = 0; it < n_iters; it++) {
        upd_gemm<<<640, 64, SMEM_BYTES>>>(W0, W1);
        upd_epi<<<1536, 256>>>(memory, inf_lr, it);
        err_gemm<<<640, 64, SMEM_BYTES>>>(W0, W1, 0);
        err_epi<<<3072, 256>>>(batch_inp, it, 0);
    }

    finalize_kernel<<<1, MAX_ITERS>>>((float*)d_out, n_iters);
}

// round 10
// speedup vs baseline: 1.1310x; 1.1310x over previous
#include <cuda_runtime.h>
#include <math.h>
#include <stdint.h>

// ---------------------------------------------------------------------------
// Problem constants
// ---------------------------------------------------------------------------
constexpr int BATCH = 256;
constexpr int N0 = 2048;
constexpr int N1 = 4096;
constexpr int N2 = 8192;
constexpr float LAMB = 0.5f;
constexpr int MAX_ITERS = 64;

// ---------------------------------------------------------------------------
// Persistent state + split-K scratch + weight splits (__device__ globals).
// RULE (learned R3/R4/R9): device globals may ONLY be referenced from device
// code — never passed as kernel arguments from host (host sees the shadow
// symbol; ATS makes the bogus write succeed silently).
// ---------------------------------------------------------------------------
__device__ float g_v0[BATCH * N0], g_t0[BATCH * N0], g_e0[BATCH * N0];
__device__ float g_v1[BATCH * N1], g_t1[BATCH * N1], g_e1[BATCH * N1];
__device__ float g_e2[BATCH * N2];
__device__ float sP0[2][BATCH * N0];   // e1@W0 partials (UPD0)
__device__ float sP1[4][BATCH * N1];   // e2@W1 partials (UPD1)
__device__ float sQ1[BATCH * N1];      // t0@W0^T (FWD1/ERR1)
__device__ float sQ2[2][BATCH * N2];   // t1@W1^T partials (ERR2)
__device__ float g_W0hi[(size_t)N1 * N0], g_W0lo[(size_t)N1 * N0];
__device__ float g_W1hi[(size_t)N2 * N1], g_W1lo[(size_t)N2 * N1];
__device__ double g_loss[MAX_ITERS];

// ---------------------------------------------------------------------------
// PTX helpers (sm_80 baseline; ptxas target is plain sm_103)
// ---------------------------------------------------------------------------
__device__ __forceinline__ uint32_t s2u(const void* p) {
    uint32_t a;
    asm("{ .reg .u64 t; cvta.to.shared.u64 t, %1; cvt.u32.u64 %0, t; }"
        : "=r"(a) : "l"(p));
    return a;
}
__device__ __forceinline__ void cp_async16(uint32_t saddr, const void* gaddr) {
    asm volatile("cp.async.cg.shared.global [%0], [%1], 16;"
                 :: "r"(saddr), "l"(gaddr) : "memory");
}
__device__ __forceinline__ void cp_commit() {
    asm volatile("cp.async.commit_group;" ::: "memory");
}
template <int N>
__device__ __forceinline__ void cp_wait() {
    asm volatile("cp.async.wait_group %0;" :: "n"(N) : "memory");
}
__device__ __forceinline__ void mma_tf32(float* d, const uint32_t* a, const uint32_t* b) {
    asm volatile(
        "mma.sync.aligned.m16n8k8.row.col.f32.tf32.tf32.f32 "
        "{%0,%1,%2,%3}, {%4,%5,%6,%7}, {%8,%9}, {%0,%1,%2,%3};"
        : "+f"(d[0]), "+f"(d[1]), "+f"(d[2]), "+f"(d[3])
        : "r"(a[0]), "r"(a[1]), "r"(a[2]), "r"(a[3]), "r"(b[0]), "r"(b[1]));
}
__device__ __forceinline__ void split_tf32(float x, uint32_t& h, uint32_t& l) {
    uint32_t hu;
    asm("cvt.rna.tf32.f32 %0, %1;" : "=r"(hu) : "f"(x));
    float hf = __uint_as_float(hu);
    uint32_t lu;
    asm("cvt.rna.tf32.f32 %0, %1;" : "=r"(lu) : "f"(x - hf));
    h = hu;
    l = lu;
}

// ---------------------------------------------------------------------------
// prep: weight hi/lo splits. Output arrays selected in DEVICE code.
// which=0 -> W0 (8.4M elems), which=1 -> W1 (33.6M elems)
// ---------------------------------------------------------------------------
__global__ void split_w_k(const float* __restrict__ W, int which, int n) {
    float* __restrict__ hi = which ? g_W1hi : g_W0hi;
    float* __restrict__ lo = which ? g_W1lo : g_W0lo;
    int i0 = blockIdx.x * blockDim.x + threadIdx.x;
    int stride = gridDim.x * blockDim.x;
    for (int i = i0; i < n; i += stride) {
        uint32_t h, l;
        split_tf32(W[i], h, l);
        hi[i] = __uint_as_float(h);
        lo[i] = __uint_as_float(l);
    }
}

// ---------------------------------------------------------------------------
// init
// ---------------------------------------------------------------------------
__global__ void init_state_k(const float* __restrict__ memory) {
    int i0 = blockIdx.x * blockDim.x + threadIdx.x;
    int stride = gridDim.x * blockDim.x;
    if (i0 < MAX_ITERS) g_loss[i0] = 0.0;
    for (int i = i0; i < BATCH * N0; i += stride) {
        float m = memory[i & (N0 - 1)];
        g_v0[i] = m;
        g_t0[i] = tanhf(m);
        g_e0[i] = 0.0f;
    }
    for (int i = i0; i < BATCH * N1; i += stride) g_e1[i] = 0.0f;
}

// ---------------------------------------------------------------------------
// Split-K GEMM (pure partial writer), 3xTF32; A split on-the-fly, B pre-split.
// CTA tile 64x64, 2 warps (each 32x64), KC=32, 2-stage cp.async (3 streams:
// A raw, Bhi, Blo), KPART=2048. 4 CTAs/SM.
// Modes: 0: t0@W0^T -> sQ1     (BT, K=N0)
//        1: t1@W1^T -> sQ2[p]  (BT, K=N1, 2 parts)
//        2: e1@W0   -> sP0[p]  (NN, K=N1, 2 parts)
//        3: e2@W1   -> sP1[p]  (NN, K=N2, 4 parts)
// ---------------------------------------------------------------------------
constexpr int KC = 32, KPART = 2048;
constexpr int LDA = 36;    // A smem stride (rows = m)
constexpr int LDBT = 36;   // B smem stride, BT (rows = n)
constexpr int LDBN = 72;   // B smem stride, NN (rows = k)
constexpr int ASZ = 64 * LDA;                  // 2304 floats
constexpr int BSZ = 2304;                      // 64*36 = 32*72
constexpr int STAGE_F = ASZ + 2 * BSZ;         // 6912 floats
constexpr int SMEM_BYTES = 2 * STAGE_F * 4;    // 55296 B

template <int MODE>
__device__ __forceinline__ void gemm_body(int bx, int by, int part) {
    constexpr bool BT = (MODE == 0 || MODE == 1);
    constexpr int NF = (MODE == 0) ? N1 : (MODE == 1) ? N2 : (MODE == 2) ? N0 : N1;
    constexpr int KF = (MODE == 0) ? N0 : (MODE == 1) ? N1 : (MODE == 2) ? N1 : N2;
    constexpr int NCH = KPART / KC;  // 64

    const float* __restrict__ Ag =
        (MODE == 0) ? g_t0 : (MODE == 1) ? g_t1 : (MODE == 2) ? g_e1 : g_e2;
    const float* __restrict__ Whi =
        (MODE == 0 || MODE == 2) ? g_W0hi : g_W1hi;
    const float* __restrict__ Wlo =
        (MODE == 0 || MODE == 2) ? g_W0lo : g_W1lo;
    float* __restrict__ dst =
        (MODE == 0) ? sQ1 : (MODE == 1) ? sQ2[part]
        : (MODE == 2) ? sP0[part] : sP1[part];

    extern __shared__ float sm[];
    const uint32_t sb = s2u(sm);
    const int tid = threadIdx.x;
    const int wid = tid >> 5;   // 0..1 (m-warp)
    const int lane = tid & 31;
    const int tq = lane >> 2;   // 0..7
    const int tr = lane & 3;    // 0..3
    const int bm = by * 64;
    const int bn = bx * 64;

    auto load_chunk = [&](int c, int st) {
        const int kt = part * KPART + c * KC;
        uint32_t sA = sb + (uint32_t)st * STAGE_F * 4;
#pragma unroll
        for (int i = 0; i < 8; i++) {
            int f = tid + i * 64;
            int row = f >> 3, seg = f & 7;
            cp_async16(sA + row * (LDA * 4) + seg * 16,
                       Ag + (size_t)(bm + row) * KF + kt + seg * 4);
        }
        uint32_t sBh = sA + ASZ * 4;
        uint32_t sBl = sBh + BSZ * 4;
        if (BT) {
            // 64 n-rows x 32 k, two streams
#pragma unroll
            for (int i = 0; i < 8; i++) {
                int f = tid + i * 64;
                int row = f >> 3, seg = f & 7;
                size_t go = (size_t)(bn + row) * KF + kt + seg * 4;
                uint32_t so = row * (LDBT * 4) + seg * 16;
                cp_async16(sBh + so, Whi + go);
                cp_async16(sBl + so, Wlo + go);
            }
        } else {
            // 32 k-rows x 64 n, two streams
#pragma unroll
            for (int i = 0; i < 8; i++) {
                int f = tid + i * 64;
                int row = f >> 4, seg = f & 15;
                size_t go = (size_t)(kt + row) * NF + bn + seg * 4;
                uint32_t so = row * (LDBN * 4) + seg * 16;
                cp_async16(sBh + so, Whi + go);
                cp_async16(sBl + so, Wlo + go);
            }
        }
        cp_commit();
    };

    float d[2][8][4];
#pragma unroll
    for (int mi = 0; mi < 2; mi++)
#pragma unroll
        for (int ni = 0; ni < 8; ni++)
#pragma unroll
            for (int r = 0; r < 4; r++) d[mi][ni][r] = 0.0f;

    load_chunk(0, 0);

    for (int c = 0; c < NCH; c++) {
        cp_wait<0>();
        __syncthreads();   // orders compute of c-1 before overwrite of its stage
        int nc = c + 1;
        if (nc < NCH) load_chunk(nc, nc & 1);

        const float* As = sm + (c & 1) * STAGE_F;
        const float* Bh = As + ASZ;
        const float* Bl = Bh + BSZ;
#pragma unroll
        for (int step = 0; step < KC / 8; step++) {
            const int kk = step * 8;
            uint32_t aH[2][4], aL[2][4];
#pragma unroll
            for (int mi = 0; mi < 2; mi++) {
                int r = wid * 32 + mi * 16 + tq;
                split_tf32(As[r * LDA + kk + tr],           aH[mi][0], aL[mi][0]);
                split_tf32(As[(r + 8) * LDA + kk + tr],     aH[mi][1], aL[mi][1]);
                split_tf32(As[r * LDA + kk + tr + 4],       aH[mi][2], aL[mi][2]);
                split_tf32(As[(r + 8) * LDA + kk + tr + 4], aH[mi][3], aL[mi][3]);
            }
            uint32_t bH[8][2], bL[8][2];
#pragma unroll
            for (int ni = 0; ni < 8; ni++) {
                int n = ni * 8 + tq;
                if (BT) {
                    bH[ni][0] = __float_as_uint(Bh[n * LDBT + kk + tr]);
                    bH[ni][1] = __float_as_uint(Bh[n * LDBT + kk + tr + 4]);
                    bL[ni][0] = __float_as_uint(Bl[n * LDBT + kk + tr]);
                    bL[ni][1] = __float_as_uint(Bl[n * LDBT + kk + tr + 4]);
                } else {
                    bH[ni][0] = __float_as_uint(Bh[(kk + tr) * LDBN + n]);
                    bH[ni][1] = __float_as_uint(Bh[(kk + tr + 4) * LDBN + n]);
                    bL[ni][0] = __float_as_uint(Bl[(kk + tr) * LDBN + n]);
                    bL[ni][1] = __float_as_uint(Bl[(kk + tr + 4) * LDBN + n]);
                }
            }
#pragma unroll
            for (int mi = 0; mi < 2; mi++)
#pragma unroll
                for (int ni = 0; ni < 8; ni++) {
                    mma_tf32(d[mi][ni], aH[mi], bH[ni]);
                    mma_tf32(d[mi][ni], aH[mi], bL[ni]);
                    mma_tf32(d[mi][ni], aL[mi], bH[ni]);
                }
        }
    }

    // write partial tile (plain stores; deterministic)
#pragma unroll
    for (int mi = 0; mi < 2; mi++)
#pragma unroll
        for (int ni = 0; ni < 8; ni++)
#pragma unroll
            for (int hf = 0; hf < 2; hf++) {
                int row = bm + wid * 32 + mi * 16 + tq + hf * 8;
                int col = bn + ni * 8 + tr * 2;
                *(float2*)&dst[(size_t)row * NF + col] =
                    make_float2(d[mi][ni][hf * 2], d[mi][ni][hf * 2 + 1]);
            }
}

// ---------------------------------------------------------------------------
// Fused phase GEMM kernels (1-D grid of uniform-duration CTAs)
// upd: mode2 (2 parts x 128) + mode3 (4 x 256) = 1280
// err: mode0 (256) + mode1 (2 x 512) = 1280 (boff selects sub-range)
// ---------------------------------------------------------------------------
__global__ __launch_bounds__(64, 4)
void upd_gemm() {
    int b = blockIdx.x;
    if (b < 256) {
        int part = b >> 7, t = b & 127;
        gemm_body<2>(t & 31, t >> 5, part);
    } else {
        int b2 = b - 256;
        int part = b2 >> 8, t = b2 & 255;
        gemm_body<3>(t & 63, t >> 6, part);
    }
}
__global__ __launch_bounds__(64, 4)
void err_gemm(int boff) {
    int b = blockIdx.x + boff;
    if (b < 256) {
        gemm_body<0>(b & 63, b >> 6, 0);
    } else {
        int b2 = b - 256;
        int part = b2 >> 9, t = b2 & 511;
        gemm_body<1>(t & 127, t >> 7, part);
    }
}

// ---------------------------------------------------------------------------
// Epilogue kernels (elementwise, float4)
// ---------------------------------------------------------------------------
__device__ __forceinline__ void block_loss(float lsum, int loss_idx) {
    __shared__ float wred[8];
    int tid = threadIdx.x;
#pragma unroll
    for (int o = 16; o > 0; o >>= 1)
        lsum += __shfl_down_sync(0xffffffffu, lsum, o);
    if ((tid & 31) == 0) wred[tid >> 5] = lsum;
    __syncthreads();
    if (tid == 0 && loss_idx >= 0) {
        float s = 0.f;
#pragma unroll
        for (int w = 0; w < 8; w++) s += wred[w];
        atomicAdd(&g_loss[loss_idx], (double)s);
    }
}

// grid 1536 x 256 : v0 update (131072 f4) then v1 update (262144 f4)
__global__ __launch_bounds__(256)
void upd_epi(const float* __restrict__ memory, const float* __restrict__ lr_p,
             int loss_idx) {
    int i = blockIdx.x * blockDim.x + threadIdx.x;
    float lr = *lr_p;
    float lsum = 0.f;
    if (i < BATCH * N0 / 4) {
        float4 p0 = ((const float4*)sP0[0])[i];
        float4 p1 = ((const float4*)sP0[1])[i];
        float4 v4 = ((const float4*)g_v0)[i];
        float4 e4 = ((const float4*)g_e0)[i];
        float4 t4 = ((const float4*)g_t0)[i];
        float4 m4 = *(const float4*)&memory[(i * 4) & (N0 - 1)];
        float* p = &p0.x; float* pl = &p1.x;
        float* v = &v4.x; float* e = &e4.x; float* t = &t4.x; float* m = &m4.x;
        float4 nv4, nt4, ne4;
        float* nv = &nv4.x; float* nt = &nt4.x; float* ne = &ne4.x;
#pragma unroll
        for (int c = 0; c < 4; c++) {
            float g = p[c] + pl[c];
            float sg = (v[c] > 0.f) ? 1.f : ((v[c] < 0.f) ? -1.f : 0.f);
            float x = fmaxf(v[c] + lr * (-e[c] - LAMB * sg + (1.f - t[c] * t[c]) * g), 0.f);
            nv[c] = x;
            nt[c] = tanhf(x);
            float er = x - m[c];
            ne[c] = er;
            lsum += er * er;
        }
        ((float4*)g_v0)[i] = nv4;
        ((float4*)g_t0)[i] = nt4;
        ((float4*)g_e0)[i] = ne4;
    } else {
        int j = i - BATCH * N0 / 4;
        float4 p0 = ((const float4*)sP1[0])[j];
        float4 p1 = ((const float4*)sP1[1])[j];
        float4 p2 = ((const float4*)sP1[2])[j];
        float4 p3 = ((const float4*)sP1[3])[j];
        float4 v4 = ((const float4*)g_v1)[j];
        float4 e4 = ((const float4*)g_e1)[j];
        float4 t4 = ((const float4*)g_t1)[j];
        float* a0 = &p0.x; float* a1 = &p1.x; float* a2 = &p2.x; float* a3 = &p3.x;
        float* v = &v4.x; float* e = &e4.x; float* t = &t4.x;
        float4 nv4, nt4;
        float* nv = &nv4.x; float* nt = &nt4.x;
#pragma unroll
        for (int c = 0; c < 4; c++) {
            float g = (a0[c] + a1[c]) + (a2[c] + a3[c]);
            float x = fmaxf(v[c] + lr * (-e[c] + (1.f - t[c] * t[c]) * g), 0.f);
            nv[c] = x;
            nt[c] = tanhf(x);
        }
        ((float4*)g_v1)[j] = nv4;
        ((float4*)g_t1)[j] = nt4;
    }
    block_loss(lsum, loss_idx);
}

// grid 3072 x 256 : e1 (262144 f4, skipped when mode=1) then e2 (524288 f4)
__global__ __launch_bounds__(256)
void err_epi(const float* __restrict__ inp, int loss_idx, int mode) {
    int i = blockIdx.x * blockDim.x + threadIdx.x;
    float lsum = 0.f;
    if (i < BATCH * N1 / 4) {
        if (mode == 0) {
            float4 q = ((const float4*)sQ1)[i];
            float4 v = ((const float4*)g_v1)[i];
            float4 e = make_float4(v.x - q.x, v.y - q.y, v.z - q.z, v.w - q.w);
            ((float4*)g_e1)[i] = e;
            lsum = e.x * e.x + e.y * e.y + e.z * e.z + e.w * e.w;
        }
    } else {
        int j = i - BATCH * N1 / 4;
        float4 q0 = ((const float4*)sQ2[0])[j];
        float4 q1 = ((const float4*)sQ2[1])[j];
        float4 x = ((const float4*)inp)[j];
        float4 e = make_float4(x.x - (q0.x + q1.x), x.y - (q0.y + q1.y),
                               x.z - (q0.z + q1.z), x.w - (q0.w + q1.w));
        ((float4*)g_e2)[j] = e;
        lsum = e.x * e.x + e.y * e.y + e.z * e.z + e.w * e.w;
    }
    block_loss(lsum, loss_idx);
}

// grid 1024 x 256 : v1 = q1, t1 = tanh(q1)
__global__ __launch_bounds__(256)
void fwd_epi() {
    int i = blockIdx.x * blockDim.x + threadIdx.x;
    float4 q = ((const float4*)sQ1)[i];
    ((float4*)g_v1)[i] = q;
    float4 t = make_float4(tanhf(q.x), tanhf(q.y), tanhf(q.z), tanhf(q.w));
    ((float4*)g_t1)[i] = t;
}

__global__ void finalize_kernel(float* __restrict__ out, int n) {
    int i = threadIdx.x;
    if (i < n) out[i] = (float)(g_loss[i] * (100.0 / (double)BATCH));
}

// ---------------------------------------------------------------------------
// Launch (graph-capturable)
// Inputs: batch_inp, W0, W1, memory, n_iters, inf_lr
// ---------------------------------------------------------------------------
extern "C" void kernel_launch(void* const* d_in, const int* in_sizes, int n_in,
                              void* d_out, int out_size) {
    const float* batch_inp = (const float*)d_in[0];
    const float* W0 = (const float*)d_in[1];
    const float* W1 = (const float*)d_in[2];
    const float* memory = (const float*)d_in[3];
    const float* inf_lr = (const float*)d_in[5];

    int n_iters = out_size;
    if (n_iters > MAX_ITERS) n_iters = MAX_ITERS;

    cudaFuncSetAttribute(upd_gemm, cudaFuncAttributeMaxDynamicSharedMemorySize, SMEM_BYTES);
    cudaFuncSetAttribute(err_gemm, cudaFuncAttributeMaxDynamicSharedMemorySize, SMEM_BYTES);

    // weight splits (pure function of inputs; recomputed each call).
    // Outputs selected in device code -- see RULE above.
    split_w_k<<<2048, 256>>>(W0, 0, N1 * N0);
    split_w_k<<<4096, 256>>>(W1, 1, N2 * N1);
    init_state_k<<<512, 256>>>(memory);

    // init: v1 = t0@W0^T, t1 = tanh(v1); e1 stays exactly 0; e2 = inp - t1@W1^T
    err_gemm<<<256, 64, SMEM_BYTES>>>(0);       // mode 0 -> sQ1
    fwd_epi<<<1024, 256>>>();
    err_gemm<<<1024, 64, SMEM_BYTES>>>(256);    // mode 1 -> sQ2
    err_epi<<<3072, 256>>>(batch_inp, -1, 1);   // e2 only, no loss

    for (int it = 0; it < n_iters; it++) {
        upd_gemm<<<1280, 64, SMEM_BYTES>>>();
        upd_epi<<<1536, 256>>>(memory, inf_lr, it);
        err_gemm<<<1280, 64, SMEM_BYTES>>>(0);
        err_epi<<<3072, 256>>>(batch_inp, it, 0);
    }

    finalize_kernel<<<1, MAX_ITERS>>>((float*)d_out, n_iters);
}

// round 11
// speedup vs baseline: 1.1493x; 1.0162x over previous
#include <cuda_runtime.h>
#include <cuda_fp16.h>
#include <math.h>
#include <stdint.h>

// ---------------------------------------------------------------------------
// Problem constants
// ---------------------------------------------------------------------------
constexpr int BATCH = 256;
constexpr int N0 = 2048;
constexpr int N1 = 4096;
constexpr int N2 = 8192;
constexpr float LAMB = 0.5f;
constexpr int MAX_ITERS = 64;
constexpr float INV4096 = 1.0f / 4096.0f;

// ---------------------------------------------------------------------------
// Persistent state + scratch (__device__ globals).
// RULE (learned R3/R4/R9): device globals may ONLY be referenced from device
// code — never passed as kernel arguments from host (host sees the shadow
// symbol; ATS makes the bogus access succeed silently).
// ---------------------------------------------------------------------------
__device__ float g_v0[BATCH * N0], g_t0[BATCH * N0], g_e0[BATCH * N0];
__device__ float g_v1[BATCH * N1], g_t1[BATCH * N1], g_e1[BATCH * N1];
__device__ float sP0[2][BATCH * N0];   // e1@W0 partials (UPD0)
__device__ float sP1[4][BATCH * N1];   // e2@W1 partials (UPD1)
__device__ float sQ1[BATCH * N1];      // t0@W0^T (FWD1/ERR1)
__device__ float sQ2[2][BATCH * N2];   // t1@W1^T partials (ERR2)
// fp16-split packed activations (hi, lo*4096), 2 fp16 per u32, pairs along k
__device__ uint2 g_t0ph[BATCH * N0 / 4], g_t0pl[BATCH * N0 / 4];
__device__ uint2 g_t1ph[BATCH * N1 / 4], g_t1pl[BATCH * N1 / 4];
__device__ uint2 g_e1ph[BATCH * N1 / 4], g_e1pl[BATCH * N1 / 4];
__device__ uint2 g_e2ph[BATCH * N2 / 4], g_e2pl[BATCH * N2 / 4];
// fp16-split packed weights, both orientations
__device__ uint32_t g_W0bth[(size_t)N1 * N0 / 2], g_W0btl[(size_t)N1 * N0 / 2];
__device__ uint32_t g_W0nnh[(size_t)N1 * N0 / 2], g_W0nnl[(size_t)N1 * N0 / 2];
__device__ uint32_t g_W1bth[(size_t)N2 * N1 / 2], g_W1btl[(size_t)N2 * N1 / 2];
__device__ uint32_t g_W1nnh[(size_t)N2 * N1 / 2], g_W1nnl[(size_t)N2 * N1 / 2];
__device__ double g_loss[MAX_ITERS];

// ---------------------------------------------------------------------------
// PTX helpers (sm_80 baseline; ptxas target is plain sm_103)
// ---------------------------------------------------------------------------
__device__ __forceinline__ uint32_t s2u(const void* p) {
    uint32_t a;
    asm("{ .reg .u64 t; cvta.to.shared.u64 t, %1; cvt.u32.u64 %0, t; }"
        : "=r"(a) : "l"(p));
    return a;
}
__device__ __forceinline__ void cp_async16(uint32_t saddr, const void* gaddr) {
    asm volatile("cp.async.cg.shared.global [%0], [%1], 16;"
                 :: "r"(saddr), "l"(gaddr) : "memory");
}
__device__ __forceinline__ void cp_commit() {
    asm volatile("cp.async.commit_group;" ::: "memory");
}
template <int N>
__device__ __forceinline__ void cp_wait() {
    asm volatile("cp.async.wait_group %0;" :: "n"(N) : "memory");
}
// m16n8k16 fp16 MMA, fp32 accumulate
__device__ __forceinline__ void mma16(float* d, const uint32_t* a, const uint32_t* b) {
    asm volatile(
        "mma.sync.aligned.m16n8k16.row.col.f32.f16.f16.f32 "
        "{%0,%1,%2,%3}, {%4,%5,%6,%7}, {%8,%9}, {%0,%1,%2,%3};"
        : "+f"(d[0]), "+f"(d[1]), "+f"(d[2]), "+f"(d[3])
        : "r"(a[0]), "r"(a[1]), "r"(a[2]), "r"(a[3]), "r"(b[0]), "r"(b[1]));
}

__device__ __forceinline__ uint32_t packh2(__half a, __half b) {
    return (uint32_t)__half_as_ushort(a) | ((uint32_t)__half_as_ushort(b) << 16);
}
// split 4 consecutive fp32 into packed fp16 hi pair-words + scaled-lo pair-words
__device__ __forceinline__ void split4(float4 x, uint2& hi, uint2& lo) {
    __half h0 = __float2half_rn(x.x), h1 = __float2half_rn(x.y);
    __half h2 = __float2half_rn(x.z), h3 = __float2half_rn(x.w);
    hi.x = packh2(h0, h1);
    hi.y = packh2(h2, h3);
    float l0 = (x.x - __half2float(h0)) * 4096.f;
    float l1 = (x.y - __half2float(h1)) * 4096.f;
    float l2 = (x.z - __half2float(h2)) * 4096.f;
    float l3 = (x.w - __half2float(h3)) * 4096.f;
    lo.x = packh2(__float2half_rn(l0), __float2half_rn(l1));
    lo.y = packh2(__float2half_rn(l2), __float2half_rn(l3));
}

// ---------------------------------------------------------------------------
// prep: weight splits (device-side symbol selection per RULE)
// BT layout: [n][kpair] — pairs contiguous in W rows
// ---------------------------------------------------------------------------
__global__ void split_w_bt(const float* __restrict__ W, int which, int npairs) {
    uint32_t* __restrict__ hi = which ? g_W1bth : g_W0bth;
    uint32_t* __restrict__ lo = which ? g_W1btl : g_W0btl;
    int i0 = blockIdx.x * blockDim.x + threadIdx.x;
    int stride = gridDim.x * blockDim.x;
    for (int i = i0; i < npairs; i += stride) {
        float w0 = W[2 * i], w1 = W[2 * i + 1];
        __half h0 = __float2half_rn(w0), h1 = __float2half_rn(w1);
        hi[i] = packh2(h0, h1);
        lo[i] = packh2(__float2half_rn((w0 - __half2float(h0)) * 4096.f),
                       __float2half_rn((w1 - __half2float(h1)) * 4096.f));
    }
}
// NN layout: [kpair][n] — pair gathers two consecutive k-rows of W[k][n]
__global__ void split_w_nn(const float* __restrict__ W, int which) {
    uint32_t* __restrict__ hi = which ? g_W1nnh : g_W0nnh;
    uint32_t* __restrict__ lo = which ? g_W1nnl : g_W0nnl;
    const int N = which ? N1 : N0;
    const int npairs_total = which ? (N2 / 2) * N1 : (N1 / 2) * N0;
    int i0 = blockIdx.x * blockDim.x + threadIdx.x;
    int stride = gridDim.x * blockDim.x;
    for (int i = i0; i < npairs_total; i += stride) {
        int kp = i / N, n = i - kp * N;
        float w0 = W[(size_t)(2 * kp) * N + n];
        float w1 = W[(size_t)(2 * kp + 1) * N + n];
        __half h0 = __float2half_rn(w0), h1 = __float2half_rn(w1);
        hi[i] = packh2(h0, h1);
        lo[i] = packh2(__float2half_rn((w0 - __half2float(h0)) * 4096.f),
                       __float2half_rn((w1 - __half2float(h1)) * 4096.f));
    }
}

// ---------------------------------------------------------------------------
// init: v0/t0/e0, e1=0, all packed splits for t0 and e1, losses
// ---------------------------------------------------------------------------
__global__ void init_state_k(const float* __restrict__ memory) {
    int i0 = blockIdx.x * blockDim.x + threadIdx.x;
    int stride = gridDim.x * blockDim.x;
    if (i0 < MAX_ITERS) g_loss[i0] = 0.0;
    for (int i = i0; i < BATCH * N0 / 4; i += stride) {
        float4 m4 = *(const float4*)&memory[(i * 4) & (N0 - 1)];
        ((float4*)g_v0)[i] = m4;
        float4 t4 = make_float4(tanhf(m4.x), tanhf(m4.y), tanhf(m4.z), tanhf(m4.w));
        ((float4*)g_t0)[i] = t4;
        uint2 hi, lo;
        split4(t4, hi, lo);
        g_t0ph[i] = hi;
        g_t0pl[i] = lo;
        ((float4*)g_e0)[i] = make_float4(0.f, 0.f, 0.f, 0.f);
    }
    for (int i = i0; i < BATCH * N1 / 4; i += stride) {
        ((float4*)g_e1)[i] = make_float4(0.f, 0.f, 0.f, 0.f);
        g_e1ph[i] = make_uint2(0, 0);
        g_e1pl[i] = make_uint2(0, 0);
    }
}

// ---------------------------------------------------------------------------
// Split-K GEMM (pure partial writer), fp16-split emulation (~fp32 accurate).
// D = [Ah.Bh] + 2^-12 [Ah.Bl' + Al'.Bh], two fp32 accumulators.
// CTA tile 64x64, 2 warps (each 32x64), KC=32 (16 fp16-pairs), 2-stage
// cp.async, KPART=2048, 4 CTAs/SM. All operands pre-split + packed fp16x2.
// Modes: 0: t0@W0^T -> sQ1     (BT, K=N0)
//        1: t1@W1^T -> sQ2[p]  (BT, K=N1, 2 parts)
//        2: e1@W0   -> sP0[p]  (NN, K=N1, 2 parts)
//        3: e2@W1   -> sP1[p]  (NN, K=N2, 4 parts)
// ---------------------------------------------------------------------------
constexpr int KC = 32, KP = 16, KPART = 2048;
constexpr int LDA2 = 20;    // A smem stride in u32 words (rows = m)
constexpr int LDBT2 = 20;   // B smem stride, BT (rows = n)
constexpr int LDBN2 = 72;   // B smem stride, NN (rows = kpair); 72%32=8
constexpr int TILEW = 1280;                  // words per component tile
constexpr int STAGE_W = 4 * TILEW;           // Ahi,Alo,Bhi,Blo = 5120 words
constexpr int SMEM_BYTES = 2 * STAGE_W * 4;  // 40960 B

template <int MODE>
__device__ __forceinline__ void gemm_body(int bx, int by, int part) {
    constexpr bool BT = (MODE == 0 || MODE == 1);
    constexpr int NF = (MODE == 0) ? N1 : (MODE == 1) ? N2 : (MODE == 2) ? N0 : N1;
    constexpr int KF = (MODE == 0) ? N0 : (MODE == 1) ? N1 : (MODE == 2) ? N1 : N2;
    constexpr int KPF = KF / 2;      // pairs per A row
    constexpr int NCH = KPART / KC;  // 64

    const uint32_t* __restrict__ Aph = (const uint32_t*)(
        (MODE == 0) ? g_t0ph : (MODE == 1) ? g_t1ph : (MODE == 2) ? g_e1ph : g_e2ph);
    const uint32_t* __restrict__ Apl = (const uint32_t*)(
        (MODE == 0) ? g_t0pl : (MODE == 1) ? g_t1pl : (MODE == 2) ? g_e1pl : g_e2pl);
    const uint32_t* __restrict__ Bph =
        (MODE == 0) ? g_W0bth : (MODE == 1) ? g_W1bth : (MODE == 2) ? g_W0nnh : g_W1nnh;
    const uint32_t* __restrict__ Bpl =
        (MODE == 0) ? g_W0btl : (MODE == 1) ? g_W1btl : (MODE == 2) ? g_W0nnl : g_W1nnl;
    float* __restrict__ dst =
        (MODE == 0) ? sQ1 : (MODE == 1) ? sQ2[part]
        : (MODE == 2) ? sP0[part] : sP1[part];

    extern __shared__ uint32_t smw[];
    const uint32_t sb = s2u(smw);
    const int tid = threadIdx.x;
    const int wid = tid >> 5;   // 0..1 (m-warp)
    const int lane = tid & 31;
    const int tq = lane >> 2;   // 0..7
    const int tr = lane & 3;    // 0..3
    const int bm = by * 64;
    const int bn = bx * 64;

    auto load_chunk = [&](int c, int st) {
        const int ktp = part * (KPART / 2) + c * KP;  // pair offset
        uint32_t base = sb + (uint32_t)st * STAGE_W * 4;
        // A: 64 rows x 16 pairs, hi+lo (256 chunks of 16B each, 4/thread each)
#pragma unroll
        for (int i = 0; i < 4; i++) {
            int ch = tid + i * 64;
            int row = ch >> 2, cs = (ch & 3) * 4;
            size_t go = (size_t)(bm + row) * KPF + ktp + cs;
            uint32_t so = (row * LDA2 + cs) * 4;
            cp_async16(base + so, Aph + go);
            cp_async16(base + TILEW * 4 + so, Apl + go);
        }
        uint32_t bbase = base + 2 * TILEW * 4;
        if (BT) {
            // B: 64 n-rows x 16 pairs
#pragma unroll
            for (int i = 0; i < 4; i++) {
                int ch = tid + i * 64;
                int row = ch >> 2, cs = (ch & 3) * 4;
                size_t go = (size_t)(bn + row) * KPF + ktp + cs;
                uint32_t so = (row * LDBT2 + cs) * 4;
                cp_async16(bbase + so, Bph + go);
                cp_async16(bbase + TILEW * 4 + so, Bpl + go);
            }
        } else {
            // B: 16 kpair-rows x 64 n
#pragma unroll
            for (int i = 0; i < 4; i++) {
                int ch = tid + i * 64;
                int row = ch >> 4, cs = (ch & 15) * 4;
                size_t go = (size_t)(ktp + row) * NF + bn + cs;
                uint32_t so = (row * LDBN2 + cs) * 4;
                cp_async16(bbase + so, Bph + go);
                cp_async16(bbase + TILEW * 4 + so, Bpl + go);
            }
        }
        cp_commit();
    };

    float d0[2][8][4], d1[2][8][4];
#pragma unroll
    for (int mi = 0; mi < 2; mi++)
#pragma unroll
        for (int ni = 0; ni < 8; ni++)
#pragma unroll
            for (int r = 0; r < 4; r++) { d0[mi][ni][r] = 0.0f; d1[mi][ni][r] = 0.0f; }

    load_chunk(0, 0);

    for (int c = 0; c < NCH; c++) {
        cp_wait<0>();
        __syncthreads();   // orders compute of c-1 before overwrite of its stage
        int nc = c + 1;
        if (nc < NCH) load_chunk(nc, nc & 1);

        const uint32_t* Ah = smw + (c & 1) * STAGE_W;
        const uint32_t* Al = Ah + TILEW;
        const uint32_t* Bh = Ah + 2 * TILEW;
        const uint32_t* Bl = Ah + 3 * TILEW;
#pragma unroll
        for (int s = 0; s < 2; s++) {      // two k16 steps per KC=32 chunk
            const int kk = s * 8;          // pair offset within tile
            uint32_t ah[2][4], al[2][4];
#pragma unroll
            for (int mi = 0; mi < 2; mi++) {
                int r = wid * 32 + mi * 16 + tq;
                ah[mi][0] = Ah[r * LDA2 + kk + tr];
                ah[mi][1] = Ah[(r + 8) * LDA2 + kk + tr];
                ah[mi][2] = Ah[r * LDA2 + kk + tr + 4];
                ah[mi][3] = Ah[(r + 8) * LDA2 + kk + tr + 4];
                al[mi][0] = Al[r * LDA2 + kk + tr];
                al[mi][1] = Al[(r + 8) * LDA2 + kk + tr];
                al[mi][2] = Al[r * LDA2 + kk + tr + 4];
                al[mi][3] = Al[(r + 8) * LDA2 + kk + tr + 4];
            }
            uint32_t bh[8][2], bl[8][2];
#pragma unroll
            for (int ni = 0; ni < 8; ni++) {
                int n = ni * 8 + tq;
                if (BT) {
                    bh[ni][0] = Bh[n * LDBT2 + kk + tr];
                    bh[ni][1] = Bh[n * LDBT2 + kk + tr + 4];
                    bl[ni][0] = Bl[n * LDBT2 + kk + tr];
                    bl[ni][1] = Bl[n * LDBT2 + kk + tr + 4];
                } else {
                    bh[ni][0] = Bh[(kk + tr) * LDBN2 + n];
                    bh[ni][1] = Bh[(kk + tr + 4) * LDBN2 + n];
                    bl[ni][0] = Bl[(kk + tr) * LDBN2 + n];
                    bl[ni][1] = Bl[(kk + tr + 4) * LDBN2 + n];
                }
            }
#pragma unroll
            for (int mi = 0; mi < 2; mi++)
#pragma unroll
                for (int ni = 0; ni < 8; ni++) {
                    mma16(d0[mi][ni], ah[mi], bh[ni]);   // hh
                    mma16(d1[mi][ni], ah[mi], bl[ni]);   // h * lo'
                    mma16(d1[mi][ni], al[mi], bh[ni]);   // lo' * h
                }
        }
    }

    // write partial tile: D = d0 + d1 * 2^-12
#pragma unroll
    for (int mi = 0; mi < 2; mi++)
#pragma unroll
        for (int ni = 0; ni < 8; ni++)
#pragma unroll
            for (int hf = 0; hf < 2; hf++) {
                int row = bm + wid * 32 + mi * 16 + tq + hf * 8;
                int col = bn + ni * 8 + tr * 2;
                float px = d0[mi][ni][hf * 2] + d1[mi][ni][hf * 2] * INV4096;
                float py = d0[mi][ni][hf * 2 + 1] + d1[mi][ni][hf * 2 + 1] * INV4096;
                *(float2*)&dst[(size_t)row * NF + col] = make_float2(px, py);
            }
}

// ---------------------------------------------------------------------------
// Fused phase GEMM kernels (1-D grid of uniform-duration CTAs)
// upd: mode2 (2 parts x 128) + mode3 (4 x 256) = 1280
// err: mode0 (256) + mode1 (2 x 512) = 1280 (boff selects sub-range)
// ---------------------------------------------------------------------------
__global__ __launch_bounds__(64, 4)
void upd_gemm() {
    int b = blockIdx.x;
    if (b < 256) {
        int part = b >> 7, t = b & 127;
        gemm_body<2>(t & 31, t >> 5, part);
    } else {
        int b2 = b - 256;
        int part = b2 >> 8, t = b2 & 255;
        gemm_body<3>(t & 63, t >> 6, part);
    }
}
__global__ __launch_bounds__(64, 4)
void err_gemm(int boff) {
    int b = blockIdx.x + boff;
    if (b < 256) {
        gemm_body<0>(b & 63, b >> 6, 0);
    } else {
        int b2 = b - 256;
        int part = b2 >> 9, t = b2 & 511;
        gemm_body<1>(t & 127, t >> 7, part);
    }
}

// ---------------------------------------------------------------------------
// Epilogue kernels (elementwise, float4; also emit packed fp16 splits)
// ---------------------------------------------------------------------------
__device__ __forceinline__ void block_loss(float lsum, int loss_idx) {
    __shared__ float wred[8];
    int tid = threadIdx.x;
#pragma unroll
    for (int o = 16; o > 0; o >>= 1)
        lsum += __shfl_down_sync(0xffffffffu, lsum, o);
    if ((tid & 31) == 0) wred[tid >> 5] = lsum;
    __syncthreads();
    if (tid == 0 && loss_idx >= 0) {
        float s = 0.f;
#pragma unroll
        for (int w = 0; w < 8; w++) s += wred[w];
        atomicAdd(&g_loss[loss_idx], (double)s);
    }
}

// grid 1536 x 256 : v0 update (131072 f4) then v1 update (262144 f4)
__global__ __launch_bounds__(256)
void upd_epi(const float* __restrict__ memory, const float* __restrict__ lr_p,
             int loss_idx) {
    int i = blockIdx.x * blockDim.x + threadIdx.x;
    float lr = *lr_p;
    float lsum = 0.f;
    if (i < BATCH * N0 / 4) {
        float4 p0 = ((const float4*)sP0[0])[i];
        float4 p1 = ((const float4*)sP0[1])[i];
        float4 v4 = ((const float4*)g_v0)[i];
        float4 e4 = ((const float4*)g_e0)[i];
        float4 t4 = ((const float4*)g_t0)[i];
        float4 m4 = *(const float4*)&memory[(i * 4) & (N0 - 1)];
        float* p = &p0.x; float* pl = &p1.x;
        float* v = &v4.x; float* e = &e4.x; float* t = &t4.x; float* m = &m4.x;
        float4 nv4, nt4, ne4;
        float* nv = &nv4.x; float* nt = &nt4.x; float* ne = &ne4.x;
#pragma unroll
        for (int c = 0; c < 4; c++) {
            float g = p[c] + pl[c];
            float sg = (v[c] > 0.f) ? 1.f : ((v[c] < 0.f) ? -1.f : 0.f);
            float x = fmaxf(v[c] + lr * (-e[c] - LAMB * sg + (1.f - t[c] * t[c]) * g), 0.f);
            nv[c] = x;
            nt[c] = tanhf(x);
            float er = x - m[c];
            ne[c] = er;
            lsum += er * er;
        }
        ((float4*)g_v0)[i] = nv4;
        ((float4*)g_t0)[i] = nt4;
        ((float4*)g_e0)[i] = ne4;
        uint2 hi, lo;
        split4(nt4, hi, lo);
        g_t0ph[i] = hi;
        g_t0pl[i] = lo;
    } else {
        int j = i - BATCH * N0 / 4;
        float4 p0 = ((const float4*)sP1[0])[j];
        float4 p1 = ((const float4*)sP1[1])[j];
        float4 p2 = ((const float4*)sP1[2])[j];
        float4 p3 = ((const float4*)sP1[3])[j];
        float4 v4 = ((const float4*)g_v1)[j];
        float4 e4 = ((const float4*)g_e1)[j];
        float4 t4 = ((const float4*)g_t1)[j];
        float* a0 = &p0.x; float* a1 = &p1.x; float* a2 = &p2.x; float* a3 = &p3.x;
        float* v = &v4.x; float* e = &e4.x; float* t = &t4.x;
        float4 nv4, nt4;
        float* nv = &nv4.x; float* nt = &nt4.x;
#pragma unroll
        for (int c = 0; c < 4; c++) {
            float g = (a0[c] + a1[c]) + (a2[c] + a3[c]);
            float x = fmaxf(v[c] + lr * (-e[c] + (1.f - t[c] * t[c]) * g), 0.f);
            nv[c] = x;
            nt[c] = tanhf(x);
        }
        ((float4*)g_v1)[j] = nv4;
        ((float4*)g_t1)[j] = nt4;
        uint2 hi, lo;
        split4(nt4, hi, lo);
        g_t1ph[j] = hi;
        g_t1pl[j] = lo;
    }
    block_loss(lsum, loss_idx);
}

// grid 3072 x 256 : e1 (262144 f4, skipped when mode=1) then e2 (524288 f4)
__global__ __launch_bounds__(256)
void err_epi(const float* __restrict__ inp, int loss_idx, int mode) {
    int i = blockIdx.x * blockDim.x + threadIdx.x;
    float lsum = 0.f;
    if (i < BATCH * N1 / 4) {
        if (mode == 0) {
            float4 q = ((const float4*)sQ1)[i];
            float4 v = ((const float4*)g_v1)[i];
            float4 e = make_float4(v.x - q.x, v.y - q.y, v.z - q.z, v.w - q.w);
            ((float4*)g_e1)[i] = e;
            uint2 hi, lo;
            split4(e, hi, lo);
            g_e1ph[i] = hi;
            g_e1pl[i] = lo;
            lsum = e.x * e.x + e.y * e.y + e.z * e.z + e.w * e.w;
        }
    } else {
        int j = i - BATCH * N1 / 4;
        float4 q0 = ((const float4*)sQ2[0])[j];
        float4 q1 = ((const float4*)sQ2[1])[j];
        float4 x = ((const float4*)inp)[j];
        float4 e = make_float4(x.x - (q0.x + q1.x), x.y - (q0.y + q1.y),
                               x.z - (q0.z + q1.z), x.w - (q0.w + q1.w));
        uint2 hi, lo;
        split4(e, hi, lo);
        g_e2ph[j] = hi;
        g_e2pl[j] = lo;
        lsum = e.x * e.x + e.y * e.y + e.z * e.z + e.w * e.w;
    }
    block_loss(lsum, loss_idx);
}

// grid 1024 x 256 : v1 = q1, t1 = tanh(q1) (+ t1 splits)
__global__ __launch_bounds__(256)
void fwd_epi() {
    int i = blockIdx.x * blockDim.x + threadIdx.x;
    float4 q = ((const float4*)sQ1)[i];
    ((float4*)g_v1)[i] = q;
    float4 t = make_float4(tanhf(q.x), tanhf(q.y), tanhf(q.z), tanhf(q.w));
    ((float4*)g_t1)[i] = t;
    uint2 hi, lo;
    split4(t, hi, lo);
    g_t1ph[i] = hi;
    g_t1pl[i] = lo;
}

__global__ void finalize_kernel(float* __restrict__ out, int n) {
    int i = threadIdx.x;
    if (i < n) out[i] = (float)(g_loss[i] * (100.0 / (double)BATCH));
}

// ---------------------------------------------------------------------------
// Launch (graph-capturable)
// Inputs: batch_inp, W0, W1, memory, n_iters, inf_lr
// ---------------------------------------------------------------------------
extern "C" void kernel_launch(void* const* d_in, const int* in_sizes, int n_in,
                              void* d_out, int out_size) {
    const float* batch_inp = (const float*)d_in[0];
    const float* W0 = (const float*)d_in[1];
    const float* W1 = (const float*)d_in[2];
    const float* memory = (const float*)d_in[3];
    const float* inf_lr = (const float*)d_in[5];

    int n_iters = out_size;
    if (n_iters > MAX_ITERS) n_iters = MAX_ITERS;

    cudaFuncSetAttribute(upd_gemm, cudaFuncAttributeMaxDynamicSharedMemorySize, SMEM_BYTES);
    cudaFuncSetAttribute(err_gemm, cudaFuncAttributeMaxDynamicSharedMemorySize, SMEM_BYTES);

    // weight splits (pure function of inputs; recomputed each call)
    split_w_bt<<<2048, 256>>>(W0, 0, N1 * N0 / 2);
    split_w_bt<<<4096, 256>>>(W1, 1, N2 * N1 / 2);
    split_w_nn<<<2048, 256>>>(W0, 0);
    split_w_nn<<<4096, 256>>>(W1, 1);
    init_state_k<<<512, 256>>>(memory);

    // init: v1 = t0@W0^T, t1 = tanh(v1); e1 stays exactly 0; e2 = inp - t1@W1^T
    err_gemm<<<256, 64, SMEM_BYTES>>>(0);       // mode 0 -> sQ1
    fwd_epi<<<1024, 256>>>();
    err_gemm<<<1024, 64, SMEM_BYTES>>>(256);    // mode 1 -> sQ2
    err_epi<<<3072, 256>>>(batch_inp, -1, 1);   // e2 only, no loss

    for (int it = 0; it < n_iters; it++) {
        upd_gemm<<<1280, 64, SMEM_BYTES>>>();
        upd_epi<<<1536, 256>>>(memory, inf_lr, it);
        err_gemm<<<1280, 64, SMEM_BYTES>>>(0);
        err_epi<<<3072, 256>>>(batch_inp, it, 0);
    }

    finalize_kernel<<<1, MAX_ITERS>>>((float*)d_out, n_iters);
}

// round 12
// speedup vs baseline: 1.4127x; 1.2292x over previous
#include <cuda_runtime.h>
#include <cuda_fp16.h>
#include <math.h>
#include <stdint.h>

// ---------------------------------------------------------------------------
// Problem constants
// ---------------------------------------------------------------------------
constexpr int BATCH = 256;
constexpr int N0 = 2048;
constexpr int N1 = 4096;
constexpr int N2 = 8192;
constexpr float LAMB = 0.5f;
constexpr int MAX_ITERS = 64;
constexpr float INV4096 = 1.0f / 4096.0f;

// ---------------------------------------------------------------------------
// Persistent state + scratch (__device__ globals).
// RULE (learned R3/R4/R9): device globals may ONLY be referenced from device
// code — never passed as kernel arguments from host.
// ---------------------------------------------------------------------------
__device__ float g_v0[BATCH * N0], g_t0[BATCH * N0], g_e0[BATCH * N0];
__device__ float g_v1[BATCH * N1], g_t1[BATCH * N1], g_e1[BATCH * N1];
__device__ float sP0[2][BATCH * N0];   // e1@W0 partials (UPD0)
__device__ float sP1[4][BATCH * N1];   // e2@W1 partials (UPD1)
__device__ float sQ1[BATCH * N1];      // t0@W0^T (FWD1/ERR1)
__device__ float sQ2[2][BATCH * N2];   // t1@W1^T partials (ERR2)
// fp16-split packed activations (hi, lo*4096), 2 fp16 per u32, pairs along k
__device__ uint2 g_t0ph[BATCH * N0 / 4], g_t0pl[BATCH * N0 / 4];
__device__ uint2 g_t1ph[BATCH * N1 / 4], g_t1pl[BATCH * N1 / 4];
__device__ uint2 g_e1ph[BATCH * N1 / 4], g_e1pl[BATCH * N1 / 4];
__device__ uint2 g_e2ph[BATCH * N2 / 4], g_e2pl[BATCH * N2 / 4];
// fp16-split packed weights, both orientations
__device__ uint32_t g_W0bth[(size_t)N1 * N0 / 2], g_W0btl[(size_t)N1 * N0 / 2];
__device__ uint32_t g_W0nnh[(size_t)N1 * N0 / 2], g_W0nnl[(size_t)N1 * N0 / 2];
__device__ uint32_t g_W1bth[(size_t)N2 * N1 / 2], g_W1btl[(size_t)N2 * N1 / 2];
__device__ uint32_t g_W1nnh[(size_t)N2 * N1 / 2], g_W1nnl[(size_t)N2 * N1 / 2];
__device__ double g_loss[MAX_ITERS];

// ---------------------------------------------------------------------------
// PTX helpers (sm_80 baseline; ptxas target is plain sm_103)
// ---------------------------------------------------------------------------
__device__ __forceinline__ uint32_t s2u(const void* p) {
    uint32_t a;
    asm("{ .reg .u64 t; cvta.to.shared.u64 t, %1; cvt.u32.u64 %0, t; }"
        : "=r"(a) : "l"(p));
    return a;
}
__device__ __forceinline__ void cp_async16(uint32_t saddr, const void* gaddr) {
    asm volatile("cp.async.cg.shared.global [%0], [%1], 16;"
                 :: "r"(saddr), "l"(gaddr) : "memory");
}
__device__ __forceinline__ void cp_commit() {
    asm volatile("cp.async.commit_group;" ::: "memory");
}
template <int N>
__device__ __forceinline__ void cp_wait() {
    asm volatile("cp.async.wait_group %0;" :: "n"(N) : "memory");
}
// m16n8k16 fp16 MMA, fp32 accumulate
__device__ __forceinline__ void mma16(float* d, const uint32_t* a, const uint32_t* b) {
    asm volatile(
        "mma.sync.aligned.m16n8k16.row.col.f32.f16.f16.f32 "
        "{%0,%1,%2,%3}, {%4,%5,%6,%7}, {%8,%9}, {%0,%1,%2,%3};"
        : "+f"(d[0]), "+f"(d[1]), "+f"(d[2]), "+f"(d[3])
        : "r"(a[0]), "r"(a[1]), "r"(a[2]), "r"(a[3]), "r"(b[0]), "r"(b[1]));
}

__device__ __forceinline__ uint32_t packh2(__half a, __half b) {
    return (uint32_t)__half_as_ushort(a) | ((uint32_t)__half_as_ushort(b) << 16);
}
// split 4 consecutive fp32 into packed fp16 hi pair-words + scaled-lo pair-words
__device__ __forceinline__ void split4(float4 x, uint2& hi, uint2& lo) {
    __half h0 = __float2half_rn(x.x), h1 = __float2half_rn(x.y);
    __half h2 = __float2half_rn(x.z), h3 = __float2half_rn(x.w);
    hi.x = packh2(h0, h1);
    hi.y = packh2(h2, h3);
    float l0 = (x.x - __half2float(h0)) * 4096.f;
    float l1 = (x.y - __half2float(h1)) * 4096.f;
    float l2 = (x.z - __half2float(h2)) * 4096.f;
    float l3 = (x.w - __half2float(h3)) * 4096.f;
    lo.x = packh2(__float2half_rn(l0), __float2half_rn(l1));
    lo.y = packh2(__float2half_rn(l2), __float2half_rn(l3));
}

// ---------------------------------------------------------------------------
// prep: weight splits (device-side symbol selection per RULE)
// ---------------------------------------------------------------------------
__global__ void split_w_bt(const float* __restrict__ W, int which, int npairs) {
    uint32_t* __restrict__ hi = which ? g_W1bth : g_W0bth;
    uint32_t* __restrict__ lo = which ? g_W1btl : g_W0btl;
    int i0 = blockIdx.x * blockDim.x + threadIdx.x;
    int stride = gridDim.x * blockDim.x;
    for (int i = i0; i < npairs; i += stride) {
        float w0 = W[2 * i], w1 = W[2 * i + 1];
        __half h0 = __float2half_rn(w0), h1 = __float2half_rn(w1);
        hi[i] = packh2(h0, h1);
        lo[i] = packh2(__float2half_rn((w0 - __half2float(h0)) * 4096.f),
                       __float2half_rn((w1 - __half2float(h1)) * 4096.f));
    }
}
__global__ void split_w_nn(const float* __restrict__ W, int which) {
    uint32_t* __restrict__ hi = which ? g_W1nnh : g_W0nnh;
    uint32_t* __restrict__ lo = which ? g_W1nnl : g_W0nnl;
    const int N = which ? N1 : N0;
    const int npairs_total = which ? (N2 / 2) * N1 : (N1 / 2) * N0;
    int i0 = blockIdx.x * blockDim.x + threadIdx.x;
    int stride = gridDim.x * blockDim.x;
    for (int i = i0; i < npairs_total; i += stride) {
        int kp = i / N, n = i - kp * N;
        float w0 = W[(size_t)(2 * kp) * N + n];
        float w1 = W[(size_t)(2 * kp + 1) * N + n];
        __half h0 = __float2half_rn(w0), h1 = __float2half_rn(w1);
        hi[i] = packh2(h0, h1);
        lo[i] = packh2(__float2half_rn((w0 - __half2float(h0)) * 4096.f),
                       __float2half_rn((w1 - __half2float(h1)) * 4096.f));
    }
}

// ---------------------------------------------------------------------------
// init
// ---------------------------------------------------------------------------
__global__ void init_state_k(const float* __restrict__ memory) {
    int i0 = blockIdx.x * blockDim.x + threadIdx.x;
    int stride = gridDim.x * blockDim.x;
    if (i0 < MAX_ITERS) g_loss[i0] = 0.0;
    for (int i = i0; i < BATCH * N0 / 4; i += stride) {
        float4 m4 = *(const float4*)&memory[(i * 4) & (N0 - 1)];
        ((float4*)g_v0)[i] = m4;
        float4 t4 = make_float4(tanhf(m4.x), tanhf(m4.y), tanhf(m4.z), tanhf(m4.w));
        ((float4*)g_t0)[i] = t4;
        uint2 hi, lo;
        split4(t4, hi, lo);
        g_t0ph[i] = hi;
        g_t0pl[i] = lo;
        ((float4*)g_e0)[i] = make_float4(0.f, 0.f, 0.f, 0.f);
    }
    for (int i = i0; i < BATCH * N1 / 4; i += stride) {
        ((float4*)g_e1)[i] = make_float4(0.f, 0.f, 0.f, 0.f);
        g_e1ph[i] = make_uint2(0, 0);
        g_e1pl[i] = make_uint2(0, 0);
    }
}

// ---------------------------------------------------------------------------
// Split-K GEMM (pure partial writer), fp16-split emulation (~fp32 accurate).
// D = [Ah.Bh] + 2^-12 [Ah.Bl' + Al'.Bh], two fp32 accumulators.
// CTA 64x64, 2 warps (each 32x64). KC=16 (8 fp16-pairs per chunk),
// 4-stage cp.async with cp_wait<2> -> 3 chunks in flight. KPART=2048,
// 4 CTAs/SM. All operands pre-split + packed fp16x2.
// ---------------------------------------------------------------------------
constexpr int KC = 16, KP = 8, KPART = 2048;
constexpr int LDA2 = 12;    // A smem stride in u32 words (rows = m), 8 data + 4 pad
constexpr int LDBT2 = 12;   // B smem stride, BT (rows = n)
constexpr int LDBN2 = 72;   // B smem stride, NN (rows = kpair); 72%32=8
constexpr int TILEW = 768;                   // words per component tile (64*12 = 8*72 fits)
constexpr int STAGE_W = 4 * TILEW;           // Ahi,Alo,Bhi,Blo = 3072 words (12 KB)
constexpr int STG = 4;
constexpr int SMEM_BYTES = STG * STAGE_W * 4;  // 49152 B -> 4 CTAs/SM

template <int MODE>
__device__ __forceinline__ void gemm_body(int bx, int by, int part) {
    constexpr bool BT = (MODE == 0 || MODE == 1);
    constexpr int NF = (MODE == 0) ? N1 : (MODE == 1) ? N2 : (MODE == 2) ? N0 : N1;
    constexpr int KF = (MODE == 0) ? N0 : (MODE == 1) ? N1 : (MODE == 2) ? N1 : N2;
    constexpr int KPF = KF / 2;      // pairs per A row
    constexpr int NCH = KPART / KC;  // 128

    const uint32_t* __restrict__ Aph = (const uint32_t*)(
        (MODE == 0) ? g_t0ph : (MODE == 1) ? g_t1ph : (MODE == 2) ? g_e1ph : g_e2ph);
    const uint32_t* __restrict__ Apl = (const uint32_t*)(
        (MODE == 0) ? g_t0pl : (MODE == 1) ? g_t1pl : (MODE == 2) ? g_e1pl : g_e2pl);
    const uint32_t* __restrict__ Bph =
        (MODE == 0) ? g_W0bth : (MODE == 1) ? g_W1bth : (MODE == 2) ? g_W0nnh : g_W1nnh;
    const uint32_t* __restrict__ Bpl =
        (MODE == 0) ? g_W0btl : (MODE == 1) ? g_W1btl : (MODE == 2) ? g_W0nnl : g_W1nnl;
    float* __restrict__ dst =
        (MODE == 0) ? sQ1 : (MODE == 1) ? sQ2[part]
        : (MODE == 2) ? sP0[part] : sP1[part];

    extern __shared__ uint32_t smw[];
    const uint32_t sb = s2u(smw);
    const int tid = threadIdx.x;
    const int wid = tid >> 5;   // 0..1 (m-warp)
    const int lane = tid & 31;
    const int tq = lane >> 2;   // 0..7
    const int tr = lane & 3;    // 0..3
    const int bm = by * 64;
    const int bn = bx * 64;

    auto load_chunk = [&](int c, int st) {
        const int ktp = part * (KPART / 2) + c * KP;  // pair offset
        uint32_t base = sb + (uint32_t)st * STAGE_W * 4;
        // A: 64 rows x 8 pairs, hi+lo -> 128 16B-chunks per component, 2/thread
#pragma unroll
        for (int i = 0; i < 2; i++) {
            int ch = tid + i * 64;
            int row = ch >> 1, cs = (ch & 1) * 4;
            size_t go = (size_t)(bm + row) * KPF + ktp + cs;
            uint32_t so = (row * LDA2 + cs) * 4;
            cp_async16(base + so, Aph + go);
            cp_async16(base + TILEW * 4 + so, Apl + go);
        }
        uint32_t bbase = base + 2 * TILEW * 4;
        if (BT) {
            // B: 64 n-rows x 8 pairs
#pragma unroll
            for (int i = 0; i < 2; i++) {
                int ch = tid + i * 64;
                int row = ch >> 1, cs = (ch & 1) * 4;
                size_t go = (size_t)(bn + row) * KPF + ktp + cs;
                uint32_t so = (row * LDBT2 + cs) * 4;
                cp_async16(bbase + so, Bph + go);
                cp_async16(bbase + TILEW * 4 + so, Bpl + go);
            }
        } else {
            // B: 8 kpair-rows x 64 n
#pragma unroll
            for (int i = 0; i < 2; i++) {
                int ch = tid + i * 64;
                int row = ch >> 4, cs = (ch & 15) * 4;
                size_t go = (size_t)(ktp + row) * NF + bn + cs;
                uint32_t so = (row * LDBN2 + cs) * 4;
                cp_async16(bbase + so, Bph + go);
                cp_async16(bbase + TILEW * 4 + so, Bpl + go);
            }
        }
        cp_commit();
    };

    float d0[2][8][4], d1[2][8][4];
#pragma unroll
    for (int mi = 0; mi < 2; mi++)
#pragma unroll
        for (int ni = 0; ni < 8; ni++)
#pragma unroll
            for (int r = 0; r < 4; r++) { d0[mi][ni][r] = 0.0f; d1[mi][ni][r] = 0.0f; }

    // prologue: 3 chunks in flight
    load_chunk(0, 0);
    load_chunk(1, 1);
    load_chunk(2, 2);

    for (int c = 0; c < NCH; c++) {
        cp_wait<2>();      // oldest outstanding group (chunk c) complete
        __syncthreads();   // all warps past compute of c-1 before reloading its stage
        int nc = c + 3;
        if (nc < NCH) load_chunk(nc, nc & 3);
        else cp_commit();  // keep group accounting aligned through the tail

        const uint32_t* Ah = smw + (c & 3) * STAGE_W;
        const uint32_t* Al = Ah + TILEW;
        const uint32_t* Bh = Ah + 2 * TILEW;
        const uint32_t* Bl = Ah + 3 * TILEW;

        uint32_t ah[2][4], al[2][4];
#pragma unroll
        for (int mi = 0; mi < 2; mi++) {
            int r = wid * 32 + mi * 16 + tq;
            ah[mi][0] = Ah[r * LDA2 + tr];
            ah[mi][1] = Ah[(r + 8) * LDA2 + tr];
            ah[mi][2] = Ah[r * LDA2 + tr + 4];
            ah[mi][3] = Ah[(r + 8) * LDA2 + tr + 4];
            al[mi][0] = Al[r * LDA2 + tr];
            al[mi][1] = Al[(r + 8) * LDA2 + tr];
            al[mi][2] = Al[r * LDA2 + tr + 4];
            al[mi][3] = Al[(r + 8) * LDA2 + tr + 4];
        }
        uint32_t bh[8][2], bl[8][2];
#pragma unroll
        for (int ni = 0; ni < 8; ni++) {
            int n = ni * 8 + tq;
            if (BT) {
                bh[ni][0] = Bh[n * LDBT2 + tr];
                bh[ni][1] = Bh[n * LDBT2 + tr + 4];
                bl[ni][0] = Bl[n * LDBT2 + tr];
                bl[ni][1] = Bl[n * LDBT2 + tr + 4];
            } else {
                bh[ni][0] = Bh[tr * LDBN2 + n];
                bh[ni][1] = Bh[(tr + 4) * LDBN2 + n];
                bl[ni][0] = Bl[tr * LDBN2 + n];
                bl[ni][1] = Bl[(tr + 4) * LDBN2 + n];
            }
        }
#pragma unroll
        for (int mi = 0; mi < 2; mi++)
#pragma unroll
            for (int ni = 0; ni < 8; ni++) {
                mma16(d0[mi][ni], ah[mi], bh[ni]);   // hh
                mma16(d1[mi][ni], ah[mi], bl[ni]);   // h * lo'
                mma16(d1[mi][ni], al[mi], bh[ni]);   // lo' * h
            }
    }

    // write partial tile: D = d0 + d1 * 2^-12
#pragma unroll
    for (int mi = 0; mi < 2; mi++)
#pragma unroll
        for (int ni = 0; ni < 8; ni++)
#pragma unroll
            for (int hf = 0; hf < 2; hf++) {
                int row = bm + wid * 32 + mi * 16 + tq + hf * 8;
                int col = bn + ni * 8 + tr * 2;
                float px = d0[mi][ni][hf * 2] + d1[mi][ni][hf * 2] * INV4096;
                float py = d0[mi][ni][hf * 2 + 1] + d1[mi][ni][hf * 2 + 1] * INV4096;
                *(float2*)&dst[(size_t)row * NF + col] = make_float2(px, py);
            }
}

// ---------------------------------------------------------------------------
// Fused phase GEMM kernels (1-D grid of uniform-duration CTAs)
// upd: mode2 (2 parts x 128) + mode3 (4 x 256) = 1280
// err: mode0 (256) + mode1 (2 x 512) = 1280 (boff selects sub-range)
// ---------------------------------------------------------------------------
__global__ __launch_bounds__(64, 4)
void upd_gemm() {
    int b = blockIdx.x;
    if (b < 256) {
        int part = b >> 7, t = b & 127;
        gemm_body<2>(t & 31, t >> 5, part);
    } else {
        int b2 = b - 256;
        int part = b2 >> 8, t = b2 & 255;
        gemm_body<3>(t & 63, t >> 6, part);
    }
}
__global__ __launch_bounds__(64, 4)
void err_gemm(int boff) {
    int b = blockIdx.x + boff;
    if (b < 256) {
        gemm_body<0>(b & 63, b >> 6, 0);
    } else {
        int b2 = b - 256;
        int part = b2 >> 9, t = b2 & 511;
        gemm_body<1>(t & 127, t >> 7, part);
    }
}

// ---------------------------------------------------------------------------
// Epilogue kernels (elementwise, float4; also emit packed fp16 splits)
// ---------------------------------------------------------------------------
__device__ __forceinline__ void block_loss(float lsum, int loss_idx) {
    __shared__ float wred[8];
    int tid = threadIdx.x;
#pragma unroll
    for (int o = 16; o > 0; o >>= 1)
        lsum += __shfl_down_sync(0xffffffffu, lsum, o);
    if ((tid & 31) == 0) wred[tid >> 5] = lsum;
    __syncthreads();
    if (tid == 0 && loss_idx >= 0) {
        float s = 0.f;
#pragma unroll
        for (int w = 0; w < 8; w++) s += wred[w];
        atomicAdd(&g_loss[loss_idx], (double)s);
    }
}

// grid 1536 x 256 : v0 update (131072 f4) then v1 update (262144 f4)
__global__ __launch_bounds__(256)
void upd_epi(const float* __restrict__ memory, const float* __restrict__ lr_p,
             int loss_idx) {
    int i = blockIdx.x * blockDim.x + threadIdx.x;
    float lr = *lr_p;
    float lsum = 0.f;
    if (i < BATCH * N0 / 4) {
        float4 p0 = ((const float4*)sP0[0])[i];
        float4 p1 = ((const float4*)sP0[1])[i];
        float4 v4 = ((const float4*)g_v0)[i];
        float4 e4 = ((const float4*)g_e0)[i];
        float4 t4 = ((const float4*)g_t0)[i];
        float4 m4 = *(const float4*)&memory[(i * 4) & (N0 - 1)];
        float* p = &p0.x; float* pl = &p1.x;
        float* v = &v4.x; float* e = &e4.x; float* t = &t4.x; float* m = &m4.x;
        float4 nv4, nt4, ne4;
        float* nv = &nv4.x; float* nt = &nt4.x; float* ne = &ne4.x;
#pragma unroll
        for (int c = 0; c < 4; c++) {
            float g = p[c] + pl[c];
            float sg = (v[c] > 0.f) ? 1.f : ((v[c] < 0.f) ? -1.f : 0.f);
            float x = fmaxf(v[c] + lr * (-e[c] - LAMB * sg + (1.f - t[c] * t[c]) * g), 0.f);
            nv[c] = x;
            nt[c] = tanhf(x);
            float er = x - m[c];
            ne[c] = er;
            lsum += er * er;
        }
        ((float4*)g_v0)[i] = nv4;
        ((float4*)g_t0)[i] = nt4;
        ((float4*)g_e0)[i] = ne4;
        uint2 hi, lo;
        split4(nt4, hi, lo);
        g_t0ph[i] = hi;
        g_t0pl[i] = lo;
    } else {
        int j = i - BATCH * N0 / 4;
        float4 p0 = ((const float4*)sP1[0])[j];
        float4 p1 = ((const float4*)sP1[1])[j];
        float4 p2 = ((const float4*)sP1[2])[j];
        float4 p3 = ((const float4*)sP1[3])[j];
        float4 v4 = ((const float4*)g_v1)[j];
        float4 e4 = ((const float4*)g_e1)[j];
        float4 t4 = ((const float4*)g_t1)[j];
        float* a0 = &p0.x; float* a1 = &p1.x; float* a2 = &p2.x; float* a3 = &p3.x;
        float* v = &v4.x; float* e = &e4.x; float* t = &t4.x;
        float4 nv4, nt4;
        float* nv = &nv4.x; float* nt = &nt4.x;
#pragma unroll
        for (int c = 0; c < 4; c++) {
            float g = (a0[c] + a1[c]) + (a2[c] + a3[c]);
            float x = fmaxf(v[c] + lr * (-e[c] + (1.f - t[c] * t[c]) * g), 0.f);
            nv[c] = x;
            nt[c] = tanhf(x);
        }
        ((float4*)g_v1)[j] = nv4;
        ((float4*)g_t1)[j] = nt4;
        uint2 hi, lo;
        split4(nt4, hi, lo);
        g_t1ph[j] = hi;
        g_t1pl[j] = lo;
    }
    block_loss(lsum, loss_idx);
}

// grid 3072 x 256 : e1 (262144 f4, skipped when mode=1) then e2 (524288 f4)
__global__ __launch_bounds__(256)
void err_epi(const float* __restrict__ inp, int loss_idx, int mode) {
    int i = blockIdx.x * blockDim.x + threadIdx.x;
    float lsum = 0.f;
    if (i < BATCH * N1 / 4) {
        if (mode == 0) {
            float4 q = ((const float4*)sQ1)[i];
            float4 v = ((const float4*)g_v1)[i];
            float4 e = make_float4(v.x - q.x, v.y - q.y, v.z - q.z, v.w - q.w);
            ((float4*)g_e1)[i] = e;
            uint2 hi, lo;
            split4(e, hi, lo);
            g_e1ph[i] = hi;
            g_e1pl[i] = lo;
            lsum = e.x * e.x + e.y * e.y + e.z * e.z + e.w * e.w;
        }
    } else {
        int j = i - BATCH * N1 / 4;
        float4 q0 = ((const float4*)sQ2[0])[j];
        float4 q1 = ((const float4*)sQ2[1])[j];
        float4 x = ((const float4*)inp)[j];
        float4 e = make_float4(x.x - (q0.x + q1.x), x.y - (q0.y + q1.y),
                               x.z - (q0.z + q1.z), x.w - (q0.w + q1.w));
        uint2 hi, lo;
        split4(e, hi, lo);
        g_e2ph[j] = hi;
        g_e2pl[j] = lo;
        lsum = e.x * e.x + e.y * e.y + e.z * e.z + e.w * e.w;
    }
    block_loss(lsum, loss_idx);
}

// grid 1024 x 256 : v1 = q1, t1 = tanh(q1) (+ t1 splits)
__global__ __launch_bounds__(256)
void fwd_epi() {
    int i = blockIdx.x * blockDim.x + threadIdx.x;
    float4 q = ((const float4*)sQ1)[i];
    ((float4*)g_v1)[i] = q;
    float4 t = make_float4(tanhf(q.x), tanhf(q.y), tanhf(q.z), tanhf(q.w));
    ((float4*)g_t1)[i] = t;
    uint2 hi, lo;
    split4(t, hi, lo);
    g_t1ph[i] = hi;
    g_t1pl[i] = lo;
}

__global__ void finalize_kernel(float* __restrict__ out, int n) {
    int i = threadIdx.x;
    if (i < n) out[i] = (float)(g_loss[i] * (100.0 / (double)BATCH));
}

// ---------------------------------------------------------------------------
// Launch (graph-capturable)
// Inputs: batch_inp, W0, W1, memory, n_iters, inf_lr
// ---------------------------------------------------------------------------
extern "C" void kernel_launch(void* const* d_in, const int* in_sizes, int n_in,
                              void* d_out, int out_size) {
    const float* batch_inp = (const float*)d_in[0];
    const float* W0 = (const float*)d_in[1];
    const float* W1 = (const float*)d_in[2];
    const float* memory = (const float*)d_in[3];
    const float* inf_lr = (const float*)d_in[5];

    int n_iters = out_size;
    if (n_iters > MAX_ITERS) n_iters = MAX_ITERS;

    cudaFuncSetAttribute(upd_gemm, cudaFuncAttributeMaxDynamicSharedMemorySize, SMEM_BYTES);
    cudaFuncSetAttribute(err_gemm, cudaFuncAttributeMaxDynamicSharedMemorySize, SMEM_BYTES);

    // weight splits (pure function of inputs; recomputed each call)
    split_w_bt<<<2048, 256>>>(W0, 0, N1 * N0 / 2);
    split_w_bt<<<4096, 256>>>(W1, 1, N2 * N1 / 2);
    split_w_nn<<<2048, 256>>>(W0, 0);
    split_w_nn<<<4096, 256>>>(W1, 1);
    init_state_k<<<512, 256>>>(memory);

    // init: v1 = t0@W0^T, t1 = tanh(v1); e1 stays exactly 0; e2 = inp - t1@W1^T
    err_gemm<<<256, 64, SMEM_BYTES>>>(0);       // mode 0 -> sQ1
    fwd_epi<<<1024, 256>>>();
    err_gemm<<<1024, 64, SMEM_BYTES>>>(256);    // mode 1 -> sQ2
    err_epi<<<3072, 256>>>(batch_inp, -1, 1);   // e2 only, no loss

    for (int it = 0; it < n_iters; it++) {
        upd_gemm<<<1280, 64, SMEM_BYTES>>>();
        upd_epi<<<1536, 256>>>(memory, inf_lr, it);
        err_gemm<<<1280, 64, SMEM_BYTES>>>(0);
        err_epi<<<3072, 256>>>(batch_inp, it, 0);
    }

    finalize_kernel<<<1, MAX_ITERS>>>((float*)d_out, n_iters);
}

// round 13
// speedup vs baseline: 1.4460x; 1.0236x over previous
#include <cuda_runtime.h>
#include <cuda_fp16.h>
#include <math.h>
#include <stdint.h>

// ---------------------------------------------------------------------------
// Problem constants
// ---------------------------------------------------------------------------
constexpr int BATCH = 256;
constexpr int N0 = 2048;
constexpr int N1 = 4096;
constexpr int N2 = 8192;
constexpr float LAMB = 0.5f;
constexpr int MAX_ITERS = 64;
constexpr float INV4096 = 1.0f / 4096.0f;

// ---------------------------------------------------------------------------
// Persistent state + scratch (__device__ globals).
// RULE (learned R3/R4/R9): device globals may ONLY be referenced from device
// code — never passed as kernel arguments from host.
// ---------------------------------------------------------------------------
__device__ float g_v0[BATCH * N0], g_t0[BATCH * N0], g_e0[BATCH * N0];
__device__ float g_v1[BATCH * N1], g_t1[BATCH * N1], g_e1[BATCH * N1];
__device__ float sP0[2][BATCH * N0];   // e1@W0 partials (UPD0)
__device__ float sP1[4][BATCH * N1];   // e2@W1 partials (UPD1)
__device__ float sQ1[BATCH * N1];      // t0@W0^T (FWD1/ERR1)
__device__ float sQ2[2][BATCH * N2];   // t1@W1^T partials (ERR2)
// fp16-split packed activations (hi, lo*4096), 2 fp16 per u32, pairs along k
__device__ uint2 g_t0ph[BATCH * N0 / 4], g_t0pl[BATCH * N0 / 4];
__device__ uint2 g_t1ph[BATCH * N1 / 4], g_t1pl[BATCH * N1 / 4];
__device__ uint2 g_e1ph[BATCH * N1 / 4], g_e1pl[BATCH * N1 / 4];
__device__ uint2 g_e2ph[BATCH * N2 / 4], g_e2pl[BATCH * N2 / 4];
// fp16-split packed weights, both orientations
__device__ uint32_t g_W0bth[(size_t)N1 * N0 / 2], g_W0btl[(size_t)N1 * N0 / 2];
__device__ uint32_t g_W0nnh[(size_t)N1 * N0 / 2], g_W0nnl[(size_t)N1 * N0 / 2];
__device__ uint32_t g_W1bth[(size_t)N2 * N1 / 2], g_W1btl[(size_t)N2 * N1 / 2];
__device__ uint32_t g_W1nnh[(size_t)N2 * N1 / 2], g_W1nnl[(size_t)N2 * N1 / 2];
__device__ double g_loss[MAX_ITERS];

// ---------------------------------------------------------------------------
// PTX helpers (sm_80 baseline; ptxas target is plain sm_103)
// ---------------------------------------------------------------------------
__device__ __forceinline__ uint32_t s2u(const void* p) {
    uint32_t a;
    asm("{ .reg .u64 t; cvta.to.shared.u64 t, %1; cvt.u32.u64 %0, t; }"
        : "=r"(a) : "l"(p));
    return a;
}
__device__ __forceinline__ void cp_async16(uint32_t saddr, const void* gaddr) {
    asm volatile("cp.async.cg.shared.global [%0], [%1], 16;"
                 :: "r"(saddr), "l"(gaddr) : "memory");
}
__device__ __forceinline__ void cp_commit() {
    asm volatile("cp.async.commit_group;" ::: "memory");
}
template <int N>
__device__ __forceinline__ void cp_wait() {
    asm volatile("cp.async.wait_group %0;" :: "n"(N) : "memory");
}
// m16n8k16 fp16 MMA, fp32 accumulate
__device__ __forceinline__ void mma16(float* d, const uint32_t* a, const uint32_t* b) {
    asm volatile(
        "mma.sync.aligned.m16n8k16.row.col.f32.f16.f16.f32 "
        "{%0,%1,%2,%3}, {%4,%5,%6,%7}, {%8,%9}, {%0,%1,%2,%3};"
        : "+f"(d[0]), "+f"(d[1]), "+f"(d[2]), "+f"(d[3])
        : "r"(a[0]), "r"(a[1]), "r"(a[2]), "r"(a[3]), "r"(b[0]), "r"(b[1]));
}

__device__ __forceinline__ uint32_t packh2(__half a, __half b) {
    return (uint32_t)__half_as_ushort(a) | ((uint32_t)__half_as_ushort(b) << 16);
}
// split 4 consecutive fp32 into packed fp16 hi pair-words + scaled-lo pair-words
__device__ __forceinline__ void split4(float4 x, uint2& hi, uint2& lo) {
    __half h0 = __float2half_rn(x.x), h1 = __float2half_rn(x.y);
    __half h2 = __float2half_rn(x.z), h3 = __float2half_rn(x.w);
    hi.x = packh2(h0, h1);
    hi.y = packh2(h2, h3);
    float l0 = (x.x - __half2float(h0)) * 4096.f;
    float l1 = (x.y - __half2float(h1)) * 4096.f;
    float l2 = (x.z - __half2float(h2)) * 4096.f;
    float l3 = (x.w - __half2float(h3)) * 4096.f;
    lo.x = packh2(__float2half_rn(l0), __float2half_rn(l1));
    lo.y = packh2(__float2half_rn(l2), __float2half_rn(l3));
}

// ---------------------------------------------------------------------------
// prep: weight splits (device-side symbol selection per RULE)
// ---------------------------------------------------------------------------
__global__ void split_w_bt(const float* __restrict__ W, int which, int npairs) {
    uint32_t* __restrict__ hi = which ? g_W1bth : g_W0bth;
    uint32_t* __restrict__ lo = which ? g_W1btl : g_W0btl;
    int i0 = blockIdx.x * blockDim.x + threadIdx.x;
    int stride = gridDim.x * blockDim.x;
    for (int i = i0; i < npairs; i += stride) {
        float w0 = W[2 * i], w1 = W[2 * i + 1];
        __half h0 = __float2half_rn(w0), h1 = __float2half_rn(w1);
        hi[i] = packh2(h0, h1);
        lo[i] = packh2(__float2half_rn((w0 - __half2float(h0)) * 4096.f),
                       __float2half_rn((w1 - __half2float(h1)) * 4096.f));
    }
}
__global__ void split_w_nn(const float* __restrict__ W, int which) {
    uint32_t* __restrict__ hi = which ? g_W1nnh : g_W0nnh;
    uint32_t* __restrict__ lo = which ? g_W1nnl : g_W0nnl;
    const int N = which ? N1 : N0;
    const int npairs_total = which ? (N2 / 2) * N1 : (N1 / 2) * N0;
    int i0 = blockIdx.x * blockDim.x + threadIdx.x;
    int stride = gridDim.x * blockDim.x;
    for (int i = i0; i < npairs_total; i += stride) {
        int kp = i / N, n = i - kp * N;
        float w0 = W[(size_t)(2 * kp) * N + n];
        float w1 = W[(size_t)(2 * kp + 1) * N + n];
        __half h0 = __float2half_rn(w0), h1 = __float2half_rn(w1);
        hi[i] = packh2(h0, h1);
        lo[i] = packh2(__float2half_rn((w0 - __half2float(h0)) * 4096.f),
                       __float2half_rn((w1 - __half2float(h1)) * 4096.f));
    }
}

// ---------------------------------------------------------------------------
// init
// ---------------------------------------------------------------------------
__global__ void init_state_k(const float* __restrict__ memory) {
    int i0 = blockIdx.x * blockDim.x + threadIdx.x;
    int stride = gridDim.x * blockDim.x;
    if (i0 < MAX_ITERS) g_loss[i0] = 0.0;
    for (int i = i0; i < BATCH * N0 / 4; i += stride) {
        float4 m4 = *(const float4*)&memory[(i * 4) & (N0 - 1)];
        ((float4*)g_v0)[i] = m4;
        float4 t4 = make_float4(tanhf(m4.x), tanhf(m4.y), tanhf(m4.z), tanhf(m4.w));
        ((float4*)g_t0)[i] = t4;
        uint2 hi, lo;
        split4(t4, hi, lo);
        g_t0ph[i] = hi;
        g_t0pl[i] = lo;
        ((float4*)g_e0)[i] = make_float4(0.f, 0.f, 0.f, 0.f);
    }
    for (int i = i0; i < BATCH * N1 / 4; i += stride) {
        ((float4*)g_e1)[i] = make_float4(0.f, 0.f, 0.f, 0.f);
        g_e1ph[i] = make_uint2(0, 0);
        g_e1pl[i] = make_uint2(0, 0);
    }
}

// ---------------------------------------------------------------------------
// Split-K GEMM (pure partial writer), fp16-split emulation (~fp32 accurate).
// D = [Ah.Bh] + 2^-12 [Ah.Bl' + Al'.Bh], two fp32 accumulators.
// CTA 128m x 64n, 4 m-split warps (each 32x64 — proven register footprint).
// KC=16 (8 fp16-pairs per chunk), 4-stage cp.async, cp_wait<2> (3 in flight),
// KPART=2048, 3 CTAs/SM (12 warps/SM). B traffic halved vs 64m tiles.
// Modes: 0: t0@W0^T -> sQ1     (BT, K=N0)
//        1: t1@W1^T -> sQ2[p]  (BT, K=N1, 2 parts)
//        2: e1@W0   -> sP0[p]  (NN, K=N1, 2 parts)
//        3: e2@W1   -> sP1[p]  (NN, K=N2, 4 parts)
// ---------------------------------------------------------------------------
constexpr int KC = 16, KP = 8, KPART = 2048;
constexpr int BMT = 128;     // CTA m-tile
constexpr int LDA2 = 12;     // A smem stride in u32 words (rows = m): 8 data + 4 pad
constexpr int LDBT2 = 12;    // B smem stride, BT (rows = n)
constexpr int LDBN2 = 72;    // B smem stride, NN (rows = kpair); 72%32=8
constexpr int TILEW_A = BMT * LDA2;   // 1536 words per A component
constexpr int TILEW_B = 768;          // words per B component (64*12 = 768 >= 8*72)
constexpr int STAGE_W = 2 * TILEW_A + 2 * TILEW_B;  // 4608 words (18 KB)
constexpr int STG = 4;
constexpr int SMEM_BYTES = STG * STAGE_W * 4;       // 73728 B -> 3 CTAs/SM

template <int MODE>
__device__ __forceinline__ void gemm_body(int bx, int by, int part) {
    constexpr bool BT = (MODE == 0 || MODE == 1);
    constexpr int NF = (MODE == 0) ? N1 : (MODE == 1) ? N2 : (MODE == 2) ? N0 : N1;
    constexpr int KF = (MODE == 0) ? N0 : (MODE == 1) ? N1 : (MODE == 2) ? N1 : N2;
    constexpr int KPF = KF / 2;      // pairs per A row
    constexpr int NCH = KPART / KC;  // 128

    const uint32_t* __restrict__ Aph = (const uint32_t*)(
        (MODE == 0) ? g_t0ph : (MODE == 1) ? g_t1ph : (MODE == 2) ? g_e1ph : g_e2ph);
    const uint32_t* __restrict__ Apl = (const uint32_t*)(
        (MODE == 0) ? g_t0pl : (MODE == 1) ? g_t1pl : (MODE == 2) ? g_e1pl : g_e2pl);
    const uint32_t* __restrict__ Bph =
        (MODE == 0) ? g_W0bth : (MODE == 1) ? g_W1bth : (MODE == 2) ? g_W0nnh : g_W1nnh;
    const uint32_t* __restrict__ Bpl =
        (MODE == 0) ? g_W0btl : (MODE == 1) ? g_W1btl : (MODE == 2) ? g_W0nnl : g_W1nnl;
    float* __restrict__ dst =
        (MODE == 0) ? sQ1 : (MODE == 1) ? sQ2[part]
        : (MODE == 2) ? sP0[part] : sP1[part];

    extern __shared__ uint32_t smw[];
    const uint32_t sb = s2u(smw);
    const int tid = threadIdx.x;
    const int wid = tid >> 5;   // 0..3 (m-warp)
    const int lane = tid & 31;
    const int tq = lane >> 2;   // 0..7
    const int tr = lane & 3;    // 0..3
    const int bm = by * BMT;
    const int bn = bx * 64;

    auto load_chunk = [&](int c, int st) {
        const int ktp = part * (KPART / 2) + c * KP;  // pair offset
        uint32_t base = sb + (uint32_t)st * STAGE_W * 4;
        // A: 128 rows x 8 pairs, hi+lo -> 256 16B-chunks per component, 2/thread
#pragma unroll
        for (int i = 0; i < 2; i++) {
            int ch = tid + i * 128;
            int row = ch >> 1, cs = (ch & 1) * 4;
            size_t go = (size_t)(bm + row) * KPF + ktp + cs;
            uint32_t so = (row * LDA2 + cs) * 4;
            cp_async16(base + so, Aph + go);
            cp_async16(base + TILEW_A * 4 + so, Apl + go);
        }
        uint32_t bbase = base + 2 * TILEW_A * 4;
        if (BT) {
            // B: 64 n-rows x 8 pairs -> 128 16B-chunks per component, 1/thread
            int row = tid >> 1, cs = (tid & 1) * 4;
            size_t go = (size_t)(bn + row) * KPF + ktp + cs;
            uint32_t so = (row * LDBT2 + cs) * 4;
            cp_async16(bbase + so, Bph + go);
            cp_async16(bbase + TILEW_B * 4 + so, Bpl + go);
        } else {
            // B: 8 kpair-rows x 64 n -> 128 16B-chunks per component, 1/thread
            int row = tid >> 4, cs = (tid & 15) * 4;
            size_t go = (size_t)(ktp + row) * NF + bn + cs;
            uint32_t so = (row * LDBN2 + cs) * 4;
            cp_async16(bbase + so, Bph + go);
            cp_async16(bbase + TILEW_B * 4 + so, Bpl + go);
        }
        cp_commit();
    };

    float d0[2][8][4], d1[2][8][4];
#pragma unroll
    for (int mi = 0; mi < 2; mi++)
#pragma unroll
        for (int ni = 0; ni < 8; ni++)
#pragma unroll
            for (int r = 0; r < 4; r++) { d0[mi][ni][r] = 0.0f; d1[mi][ni][r] = 0.0f; }

    // prologue: 3 chunks in flight
    load_chunk(0, 0);
    load_chunk(1, 1);
    load_chunk(2, 2);

    for (int c = 0; c < NCH; c++) {
        cp_wait<2>();      // oldest outstanding group (chunk c) complete
        __syncthreads();   // all warps past compute of c-1 before reloading its stage
        int nc = c + 3;
        if (nc < NCH) load_chunk(nc, nc & 3);
        else cp_commit();  // keep group accounting aligned through the tail

        const uint32_t* Ah = smw + (c & 3) * STAGE_W;
        const uint32_t* Al = Ah + TILEW_A;
        const uint32_t* Bh = Ah + 2 * TILEW_A;
        const uint32_t* Bl = Bh + TILEW_B;

        uint32_t ah[2][4], al[2][4];
#pragma unroll
        for (int mi = 0; mi < 2; mi++) {
            int r = wid * 32 + mi * 16 + tq;
            ah[mi][0] = Ah[r * LDA2 + tr];
            ah[mi][1] = Ah[(r + 8) * LDA2 + tr];
            ah[mi][2] = Ah[r * LDA2 + tr + 4];
            ah[mi][3] = Ah[(r + 8) * LDA2 + tr + 4];
            al[mi][0] = Al[r * LDA2 + tr];
            al[mi][1] = Al[(r + 8) * LDA2 + tr];
            al[mi][2] = Al[r * LDA2 + tr + 4];
            al[mi][3] = Al[(r + 8) * LDA2 + tr + 4];
        }
        uint32_t bh[8][2], bl[8][2];
#pragma unroll
        for (int ni = 0; ni < 8; ni++) {
            int n = ni * 8 + tq;
            if (BT) {
                bh[ni][0] = Bh[n * LDBT2 + tr];
                bh[ni][1] = Bh[n * LDBT2 + tr + 4];
                bl[ni][0] = Bl[n * LDBT2 + tr];
                bl[ni][1] = Bl[n * LDBT2 + tr + 4];
            } else {
                bh[ni][0] = Bh[tr * LDBN2 + n];
                bh[ni][1] = Bh[(tr + 4) * LDBN2 + n];
                bl[ni][0] = Bl[tr * LDBN2 + n];
                bl[ni][1] = Bl[(tr + 4) * LDBN2 + n];
            }
        }
#pragma unroll
        for (int mi = 0; mi < 2; mi++)
#pragma unroll
            for (int ni = 0; ni < 8; ni++) {
                mma16(d0[mi][ni], ah[mi], bh[ni]);   // hh
                mma16(d1[mi][ni], ah[mi], bl[ni]);   // h * lo'
                mma16(d1[mi][ni], al[mi], bh[ni]);   // lo' * h
            }
    }

    // write partial tile: D = d0 + d1 * 2^-12
#pragma unroll
    for (int mi = 0; mi < 2; mi++)
#pragma unroll
        for (int ni = 0; ni < 8; ni++)
#pragma unroll
            for (int hf = 0; hf < 2; hf++) {
                int row = bm + wid * 32 + mi * 16 + tq + hf * 8;
                int col = bn + ni * 8 + tr * 2;
                float px = d0[mi][ni][hf * 2] + d1[mi][ni][hf * 2] * INV4096;
                float py = d0[mi][ni][hf * 2 + 1] + d1[mi][ni][hf * 2 + 1] * INV4096;
                *(float2*)&dst[(size_t)row * NF + col] = make_float2(px, py);
            }
}

// ---------------------------------------------------------------------------
// Fused phase GEMM kernels (1-D grid of uniform-duration CTAs)
// m-tiles per GEMM = BATCH/128 = 2.
// upd: mode2 (2 parts x 32 x 2 = 128) + mode3 (4 x 64 x 2 = 512) = 640
// err: mode0 (64 x 2 = 128) + mode1 (2 x 128 x 2 = 512) = 640 (boff = range)
// ---------------------------------------------------------------------------
__global__ __launch_bounds__(128, 3)
void upd_gemm() {
    int b = blockIdx.x;
    if (b < 128) {
        int part = b >> 6, t = b & 63;
        gemm_body<2>(t & 31, t >> 5, part);
    } else {
        int b2 = b - 128;
        int part = b2 >> 7, t = b2 & 127;
        gemm_body<3>(t & 63, t >> 6, part);
    }
}
__global__ __launch_bounds__(128, 3)
void err_gemm(int boff) {
    int b = blockIdx.x + boff;
    if (b < 128) {
        gemm_body<0>(b & 63, b >> 6, 0);
    } else {
        int b2 = b - 128;
        int part = b2 >> 8, t = b2 & 255;
        gemm_body<1>(t & 127, t >> 7, part);
    }
}

// ---------------------------------------------------------------------------
// Epilogue kernels (elementwise, float4; also emit packed fp16 splits)
// ---------------------------------------------------------------------------
__device__ __forceinline__ void block_loss(float lsum, int loss_idx) {
    __shared__ float wred[8];
    int tid = threadIdx.x;
#pragma unroll
    for (int o = 16; o > 0; o >>= 1)
        lsum += __shfl_down_sync(0xffffffffu, lsum, o);
    if ((tid & 31) == 0) wred[tid >> 5] = lsum;
    __syncthreads();
    if (tid == 0 && loss_idx >= 0) {
        float s = 0.f;
#pragma unroll
        for (int w = 0; w < 8; w++) s += wred[w];
        atomicAdd(&g_loss[loss_idx], (double)s);
    }
}

// grid 1536 x 256 : v0 update (131072 f4) then v1 update (262144 f4)
__global__ __launch_bounds__(256)
void upd_epi(const float* __restrict__ memory, const float* __restrict__ lr_p,
             int loss_idx) {
    int i = blockIdx.x * blockDim.x + threadIdx.x;
    float lr = *lr_p;
    float lsum = 0.f;
    if (i < BATCH * N0 / 4) {
        float4 p0 = ((const float4*)sP0[0])[i];
        float4 p1 = ((const float4*)sP0[1])[i];
        float4 v4 = ((const float4*)g_v0)[i];
        float4 e4 = ((const float4*)g_e0)[i];
        float4 t4 = ((const float4*)g_t0)[i];
        float4 m4 = *(const float4*)&memory[(i * 4) & (N0 - 1)];
        float* p = &p0.x; float* pl = &p1.x;
        float* v = &v4.x; float* e = &e4.x; float* t = &t4.x; float* m = &m4.x;
        float4 nv4, nt4, ne4;
        float* nv = &nv4.x; float* nt = &nt4.x; float* ne = &ne4.x;
#pragma unroll
        for (int c = 0; c < 4; c++) {
            float g = p[c] + pl[c];
            float sg = (v[c] > 0.f) ? 1.f : ((v[c] < 0.f) ? -1.f : 0.f);
            float x = fmaxf(v[c] + lr * (-e[c] - LAMB * sg + (1.f - t[c] * t[c]) * g), 0.f);
            nv[c] = x;
            nt[c] = tanhf(x);
            float er = x - m[c];
            ne[c] = er;
            lsum += er * er;
        }
        ((float4*)g_v0)[i] = nv4;
        ((float4*)g_t0)[i] = nt4;
        ((float4*)g_e0)[i] = ne4;
        uint2 hi, lo;
        split4(nt4, hi, lo);
        g_t0ph[i] = hi;
        g_t0pl[i] = lo;
    } else {
        int j = i - BATCH * N0 / 4;
        float4 p0 = ((const float4*)sP1[0])[j];
        float4 p1 = ((const float4*)sP1[1])[j];
        float4 p2 = ((const float4*)sP1[2])[j];
        float4 p3 = ((const float4*)sP1[3])[j];
        float4 v4 = ((const float4*)g_v1)[j];
        float4 e4 = ((const float4*)g_e1)[j];
        float4 t4 = ((const float4*)g_t1)[j];
        float* a0 = &p0.x; float* a1 = &p1.x; float* a2 = &p2.x; float* a3 = &p3.x;
        float* v = &v4.x; float* e = &e4.x; float* t = &t4.x;
        float4 nv4, nt4;
        float* nv = &nv4.x; float* nt = &nt4.x;
#pragma unroll
        for (int c = 0; c < 4; c++) {
            float g = (a0[c] + a1[c]) + (a2[c] + a3[c]);
            float x = fmaxf(v[c] + lr * (-e[c] + (1.f - t[c] * t[c]) * g), 0.f);
            nv[c] = x;
            nt[c] = tanhf(x);
        }
        ((float4*)g_v1)[j] = nv4;
        ((float4*)g_t1)[j] = nt4;
        uint2 hi, lo;
        split4(nt4, hi, lo);
        g_t1ph[j] = hi;
        g_t1pl[j] = lo;
    }
    block_loss(lsum, loss_idx);
}

// grid 3072 x 256 : e1 (262144 f4, skipped when mode=1) then e2 (524288 f4)
__global__ __launch_bounds__(256)
void err_epi(const float* __restrict__ inp, int loss_idx, int mode) {
    int i = blockIdx.x * blockDim.x + threadIdx.x;
    float lsum = 0.f;
    if (i < BATCH * N1 / 4) {
        if (mode == 0) {
            float4 q = ((const float4*)sQ1)[i];
            float4 v = ((const float4*)g_v1)[i];
            float4 e = make_float4(v.x - q.x, v.y - q.y, v.z - q.z, v.w - q.w);
            ((float4*)g_e1)[i] = e;
            uint2 hi, lo;
            split4(e, hi, lo);
            g_e1ph[i] = hi;
            g_e1pl[i] = lo;
            lsum = e.x * e.x + e.y * e.y + e.z * e.z + e.w * e.w;
        }
    } else {
        int j = i - BATCH * N1 / 4;
        float4 q0 = ((const float4*)sQ2[0])[j];
        float4 q1 = ((const float4*)sQ2[1])[j];
        float4 x = ((const float4*)inp)[j];
        float4 e = make_float4(x.x - (q0.x + q1.x), x.y - (q0.y + q1.y),
                               x.z - (q0.z + q1.z), x.w - (q0.w + q1.w));
        uint2 hi, lo;
        split4(e, hi, lo);
        g_e2ph[j] = hi;
        g_e2pl[j] = lo;
        lsum = e.x * e.x + e.y * e.y + e.z * e.z + e.w * e.w;
    }
    block_loss(lsum, loss_idx);
}

// grid 1024 x 256 : v1 = q1, t1 = tanh(q1) (+ t1 splits)
__global__ __launch_bounds__(256)
void fwd_epi() {
    int i = blockIdx.x * blockDim.x + threadIdx.x;
    float4 q = ((const float4*)sQ1)[i];
    ((float4*)g_v1)[i] = q;
    float4 t = make_float4(tanhf(q.x), tanhf(q.y), tanhf(q.z), tanhf(q.w));
    ((float4*)g_t1)[i] = t;
    uint2 hi, lo;
    split4(t, hi, lo);
    g_t1ph[i] = hi;
    g_t1pl[i] = lo;
}

__global__ void finalize_kernel(float* __restrict__ out, int n) {
    int i = threadIdx.x;
    if (i < n) out[i] = (float)(g_loss[i] * (100.0 / (double)BATCH));
}

// ---------------------------------------------------------------------------
// Launch (graph-capturable)
// Inputs: batch_inp, W0, W1, memory, n_iters, inf_lr
// ---------------------------------------------------------------------------
extern "C" void kernel_launch(void* const* d_in, const int* in_sizes, int n_in,
                              void* d_out, int out_size) {
    const float* batch_inp = (const float*)d_in[0];
    const float* W0 = (const float*)d_in[1];
    const float* W1 = (const float*)d_in[2];
    const float* memory = (const float*)d_in[3];
    const float* inf_lr = (const float*)d_in[5];

    int n_iters = out_size;
    if (n_iters > MAX_ITERS) n_iters = MAX_ITERS;

    cudaFuncSetAttribute(upd_gemm, cudaFuncAttributeMaxDynamicSharedMemorySize, SMEM_BYTES);
    cudaFuncSetAttribute(err_gemm, cudaFuncAttributeMaxDynamicSharedMemorySize, SMEM_BYTES);

    // weight splits (pure function of inputs; recomputed each call)
    split_w_bt<<<2048, 256>>>(W0, 0, N1 * N0 / 2);
    split_w_bt<<<4096, 256>>>(W1, 1, N2 * N1 / 2);
    split_w_nn<<<2048, 256>>>(W0, 0);
    split_w_nn<<<4096, 256>>>(W1, 1);
    init_state_k<<<512, 256>>>(memory);

    // init: v1 = t0@W0^T, t1 = tanh(v1); e1 stays exactly 0; e2 = inp - t1@W1^T
    err_gemm<<<128, 128, SMEM_BYTES>>>(0);      // mode 0 -> sQ1
    fwd_epi<<<1024, 256>>>();
    err_gemm<<<512, 128, SMEM_BYTES>>>(128);    // mode 1 -> sQ2
    err_epi<<<3072, 256>>>(batch_inp, -1, 1);   // e2 only, no loss

    for (int it = 0; it < n_iters; it++) {
        upd_gemm<<<640, 128, SMEM_BYTES>>>();
        upd_epi<<<1536, 256>>>(memory, inf_lr, it);
        err_gemm<<<640, 128, SMEM_BYTES>>>(0);
        err_epi<<<3072, 256>>>(batch_inp, it, 0);
    }

    finalize_kernel<<<1, MAX_ITERS>>>((float*)d_out, n_iters);
}

// round 14
// speedup vs baseline: 1.6213x; 1.1212x over previous
#include <cuda_runtime.h>
#include <cuda_fp16.h>
#include <math.h>
#include <stdint.h>

// ---------------------------------------------------------------------------
// Problem constants
// ---------------------------------------------------------------------------
constexpr int BATCH = 256;
constexpr int N0 = 2048;
constexpr int N1 = 4096;
constexpr int N2 = 8192;
constexpr float LAMB = 0.5f;
constexpr int MAX_ITERS = 64;
constexpr float INV4096 = 1.0f / 4096.0f;

// ---------------------------------------------------------------------------
// Persistent state + scratch (__device__ globals).
// RULE (learned R3/R4/R9): device globals may ONLY be referenced from device
// code — never passed as kernel arguments from host.
// ---------------------------------------------------------------------------
__device__ float g_v0[BATCH * N0], g_t0[BATCH * N0], g_e0[BATCH * N0];
__device__ float g_v1[BATCH * N1], g_t1[BATCH * N1], g_e1[BATCH * N1];
__device__ float sP0[4][BATCH * N0];   // e1@W0 partials (UPD0, 4 K-parts)
__device__ float sP1[8][BATCH * N1];   // e2@W1 partials (UPD1, 8 K-parts)
__device__ float sQ1[2][BATCH * N1];   // t0@W0^T partials (FWD1/ERR1, 2 parts)
__device__ float sQ2[4][BATCH * N2];   // t1@W1^T partials (ERR2, 4 parts)
// fp16-split packed activations (hi, lo*4096), 2 fp16 per u32, pairs along k
__device__ uint2 g_t0ph[BATCH * N0 / 4], g_t0pl[BATCH * N0 / 4];
__device__ uint2 g_t1ph[BATCH * N1 / 4], g_t1pl[BATCH * N1 / 4];
__device__ uint2 g_e1ph[BATCH * N1 / 4], g_e1pl[BATCH * N1 / 4];
__device__ uint2 g_e2ph[BATCH * N2 / 4], g_e2pl[BATCH * N2 / 4];
// fp16-split packed weights, both orientations
__device__ uint32_t g_W0bth[(size_t)N1 * N0 / 2], g_W0btl[(size_t)N1 * N0 / 2];
__device__ uint32_t g_W0nnh[(size_t)N1 * N0 / 2], g_W0nnl[(size_t)N1 * N0 / 2];
__device__ uint32_t g_W1bth[(size_t)N2 * N1 / 2], g_W1btl[(size_t)N2 * N1 / 2];
__device__ uint32_t g_W1nnh[(size_t)N2 * N1 / 2], g_W1nnl[(size_t)N2 * N1 / 2];
__device__ double g_loss[MAX_ITERS];

// ---------------------------------------------------------------------------
// PTX helpers (sm_80 baseline; ptxas target is plain sm_103)
// ---------------------------------------------------------------------------
__device__ __forceinline__ uint32_t s2u(const void* p) {
    uint32_t a;
    asm("{ .reg .u64 t; cvta.to.shared.u64 t, %1; cvt.u32.u64 %0, t; }"
        : "=r"(a) : "l"(p));
    return a;
}
__device__ __forceinline__ void cp_async16(uint32_t saddr, const void* gaddr) {
    asm volatile("cp.async.cg.shared.global [%0], [%1], 16;"
                 :: "r"(saddr), "l"(gaddr) : "memory");
}
__device__ __forceinline__ void cp_commit() {
    asm volatile("cp.async.commit_group;" ::: "memory");
}
template <int N>
__device__ __forceinline__ void cp_wait() {
    asm volatile("cp.async.wait_group %0;" :: "n"(N) : "memory");
}
// m16n8k16 fp16 MMA, fp32 accumulate
__device__ __forceinline__ void mma16(float* d, const uint32_t* a, const uint32_t* b) {
    asm volatile(
        "mma.sync.aligned.m16n8k16.row.col.f32.f16.f16.f32 "
        "{%0,%1,%2,%3}, {%4,%5,%6,%7}, {%8,%9}, {%0,%1,%2,%3};"
        : "+f"(d[0]), "+f"(d[1]), "+f"(d[2]), "+f"(d[3])
        : "r"(a[0]), "r"(a[1]), "r"(a[2]), "r"(a[3]), "r"(b[0]), "r"(b[1]));
}

__device__ __forceinline__ uint32_t packh2(__half a, __half b) {
    return (uint32_t)__half_as_ushort(a) | ((uint32_t)__half_as_ushort(b) << 16);
}
// split 4 consecutive fp32 into packed fp16 hi pair-words + scaled-lo pair-words
__device__ __forceinline__ void split4(float4 x, uint2& hi, uint2& lo) {
    __half h0 = __float2half_rn(x.x), h1 = __float2half_rn(x.y);
    __half h2 = __float2half_rn(x.z), h3 = __float2half_rn(x.w);
    hi.x = packh2(h0, h1);
    hi.y = packh2(h2, h3);
    float l0 = (x.x - __half2float(h0)) * 4096.f;
    float l1 = (x.y - __half2float(h1)) * 4096.f;
    float l2 = (x.z - __half2float(h2)) * 4096.f;
    float l3 = (x.w - __half2float(h3)) * 4096.f;
    lo.x = packh2(__float2half_rn(l0), __float2half_rn(l1));
    lo.y = packh2(__float2half_rn(l2), __float2half_rn(l3));
}

// ---------------------------------------------------------------------------
// prep: weight splits (device-side symbol selection per RULE)
// ---------------------------------------------------------------------------
__global__ void split_w_bt(const float* __restrict__ W, int which, int npairs) {
    uint32_t* __restrict__ hi = which ? g_W1bth : g_W0bth;
    uint32_t* __restrict__ lo = which ? g_W1btl : g_W0btl;
    int i0 = blockIdx.x * blockDim.x + threadIdx.x;
    int stride = gridDim.x * blockDim.x;
    for (int i = i0; i < npairs; i += stride) {
        float w0 = W[2 * i], w1 = W[2 * i + 1];
        __half h0 = __float2half_rn(w0), h1 = __float2half_rn(w1);
        hi[i] = packh2(h0, h1);
        lo[i] = packh2(__float2half_rn((w0 - __half2float(h0)) * 4096.f),
                       __float2half_rn((w1 - __half2float(h1)) * 4096.f));
    }
}
__global__ void split_w_nn(const float* __restrict__ W, int which) {
    uint32_t* __restrict__ hi = which ? g_W1nnh : g_W0nnh;
    uint32_t* __restrict__ lo = which ? g_W1nnl : g_W0nnl;
    const int N = which ? N1 : N0;
    const int npairs_total = which ? (N2 / 2) * N1 : (N1 / 2) * N0;
    int i0 = blockIdx.x * blockDim.x + threadIdx.x;
    int stride = gridDim.x * blockDim.x;
    for (int i = i0; i < npairs_total; i += stride) {
        int kp = i / N, n = i - kp * N;
        float w0 = W[(size_t)(2 * kp) * N + n];
        float w1 = W[(size_t)(2 * kp + 1) * N + n];
        __half h0 = __float2half_rn(w0), h1 = __float2half_rn(w1);
        hi[i] = packh2(h0, h1);
        lo[i] = packh2(__float2half_rn((w0 - __half2float(h0)) * 4096.f),
                       __float2half_rn((w1 - __half2float(h1)) * 4096.f));
    }
}

// ---------------------------------------------------------------------------
// init
// ---------------------------------------------------------------------------
__global__ void init_state_k(const float* __restrict__ memory) {
    int i0 = blockIdx.x * blockDim.x + threadIdx.x;
    int stride = gridDim.x * blockDim.x;
    if (i0 < MAX_ITERS) g_loss[i0] = 0.0;
    for (int i = i0; i < BATCH * N0 / 4; i += stride) {
        float4 m4 = *(const float4*)&memory[(i * 4) & (N0 - 1)];
        ((float4*)g_v0)[i] = m4;
        float4 t4 = make_float4(tanhf(m4.x), tanhf(m4.y), tanhf(m4.z), tanhf(m4.w));
        ((float4*)g_t0)[i] = t4;
        uint2 hi, lo;
        split4(t4, hi, lo);
        g_t0ph[i] = hi;
        g_t0pl[i] = lo;
        ((float4*)g_e0)[i] = make_float4(0.f, 0.f, 0.f, 0.f);
    }
    for (int i = i0; i < BATCH * N1 / 4; i += stride) {
        ((float4*)g_e1)[i] = make_float4(0.f, 0.f, 0.f, 0.f);
        g_e1ph[i] = make_uint2(0, 0);
        g_e1pl[i] = make_uint2(0, 0);
    }
}

// ---------------------------------------------------------------------------
// Split-K GEMM (pure partial writer), fp16-split emulation (~fp32 accurate).
// D = [Ah.Bh] + 2^-12 [Ah.Bl' + Al'.Bh], two fp32 accumulators.
// CTA 128m x 64n, 4 m-split warps (each 32x64). KC=16, 4-stage cp.async,
// cp_wait<2>. KPART=1024 (fine work quanta -> 2.88 waves, ~4% tail).
// 3 CTAs/SM.
// Modes: 0: t0@W0^T -> sQ1[p]  (BT, K=N0, 2 parts)
//        1: t1@W1^T -> sQ2[p]  (BT, K=N1, 4 parts)
//        2: e1@W0   -> sP0[p]  (NN, K=N1, 4 parts)
//        3: e2@W1   -> sP1[p]  (NN, K=N2, 8 parts)
// ---------------------------------------------------------------------------
constexpr int KC = 16, KP = 8, KPART = 1024;
constexpr int BMT = 128;     // CTA m-tile
constexpr int LDA2 = 12;     // A smem stride in u32 words (rows = m)
constexpr int LDBT2 = 12;    // B smem stride, BT (rows = n)
constexpr int LDBN2 = 72;    // B smem stride, NN (rows = kpair); 72%32=8
constexpr int TILEW_A = BMT * LDA2;   // 1536 words per A component
constexpr int TILEW_B = 768;          // words per B component
constexpr int STAGE_W = 2 * TILEW_A + 2 * TILEW_B;  // 4608 words (18 KB)
constexpr int STG = 4;
constexpr int SMEM_BYTES = STG * STAGE_W * 4;       // 73728 B -> 3 CTAs/SM

template <int MODE>
__device__ __forceinline__ void gemm_body(int bx, int by, int part) {
    constexpr bool BT = (MODE == 0 || MODE == 1);
    constexpr int NF = (MODE == 0) ? N1 : (MODE == 1) ? N2 : (MODE == 2) ? N0 : N1;
    constexpr int KF = (MODE == 0) ? N0 : (MODE == 1) ? N1 : (MODE == 2) ? N1 : N2;
    constexpr int KPF = KF / 2;      // pairs per A row
    constexpr int NCH = KPART / KC;  // 64

    const uint32_t* __restrict__ Aph = (const uint32_t*)(
        (MODE == 0) ? g_t0ph : (MODE == 1) ? g_t1ph : (MODE == 2) ? g_e1ph : g_e2ph);
    const uint32_t* __restrict__ Apl = (const uint32_t*)(
        (MODE == 0) ? g_t0pl : (MODE == 1) ? g_t1pl : (MODE == 2) ? g_e1pl : g_e2pl);
    const uint32_t* __restrict__ Bph =
        (MODE == 0) ? g_W0bth : (MODE == 1) ? g_W1bth : (MODE == 2) ? g_W0nnh : g_W1nnh;
    const uint32_t* __restrict__ Bpl =
        (MODE == 0) ? g_W0btl : (MODE == 1) ? g_W1btl : (MODE == 2) ? g_W0nnl : g_W1nnl;
    float* __restrict__ dst =
        (MODE == 0) ? sQ1[part] : (MODE == 1) ? sQ2[part]
        : (MODE == 2) ? sP0[part] : sP1[part];

    extern __shared__ uint32_t smw[];
    const uint32_t sb = s2u(smw);
    const int tid = threadIdx.x;
    const int wid = tid >> 5;   // 0..3 (m-warp)
    const int lane = tid & 31;
    const int tq = lane >> 2;   // 0..7
    const int tr = lane & 3;    // 0..3
    const int bm = by * BMT;
    const int bn = bx * 64;

    auto load_chunk = [&](int c, int st) {
        const int ktp = part * (KPART / 2) + c * KP;  // pair offset
        uint32_t base = sb + (uint32_t)st * STAGE_W * 4;
        // A: 128 rows x 8 pairs, hi+lo -> 256 16B-chunks per component, 2/thread
#pragma unroll
        for (int i = 0; i < 2; i++) {
            int ch = tid + i * 128;
            int row = ch >> 1, cs = (ch & 1) * 4;
            size_t go = (size_t)(bm + row) * KPF + ktp + cs;
            uint32_t so = (row * LDA2 + cs) * 4;
            cp_async16(base + so, Aph + go);
            cp_async16(base + TILEW_A * 4 + so, Apl + go);
        }
        uint32_t bbase = base + 2 * TILEW_A * 4;
        if (BT) {
            // B: 64 n-rows x 8 pairs -> 128 16B-chunks per component, 1/thread
            int row = tid >> 1, cs = (tid & 1) * 4;
            size_t go = (size_t)(bn + row) * KPF + ktp + cs;
            uint32_t so = (row * LDBT2 + cs) * 4;
            cp_async16(bbase + so, Bph + go);
            cp_async16(bbase + TILEW_B * 4 + so, Bpl + go);
        } else {
            // B: 8 kpair-rows x 64 n -> 128 16B-chunks per component, 1/thread
            int row = tid >> 4, cs = (tid & 15) * 4;
            size_t go = (size_t)(ktp + row) * NF + bn + cs;
            uint32_t so = (row * LDBN2 + cs) * 4;
            cp_async16(bbase + so, Bph + go);
            cp_async16(bbase + TILEW_B * 4 + so, Bpl + go);
        }
        cp_commit();
    };

    float d0[2][8][4], d1[2][8][4];
#pragma unroll
    for (int mi = 0; mi < 2; mi++)
#pragma unroll
        for (int ni = 0; ni < 8; ni++)
#pragma unroll
            for (int r = 0; r < 4; r++) { d0[mi][ni][r] = 0.0f; d1[mi][ni][r] = 0.0f; }

    // prologue: 3 chunks in flight
    load_chunk(0, 0);
    load_chunk(1, 1);
    load_chunk(2, 2);

    for (int c = 0; c < NCH; c++) {
        cp_wait<2>();      // oldest outstanding group (chunk c) complete
        __syncthreads();   // all warps past compute of c-1 before reloading its stage
        int nc = c + 3;
        if (nc < NCH) load_chunk(nc, nc & 3);
        else cp_commit();  // keep group accounting aligned through the tail

        const uint32_t* Ah = smw + (c & 3) * STAGE_W;
        const uint32_t* Al = Ah + TILEW_A;
        const uint32_t* Bh = Ah + 2 * TILEW_A;
        const uint32_t* Bl = Bh + TILEW_B;

        uint32_t ah[2][4], al[2][4];
#pragma unroll
        for (int mi = 0; mi < 2; mi++) {
            int r = wid * 32 + mi * 16 + tq;
            ah[mi][0] = Ah[r * LDA2 + tr];
            ah[mi][1] = Ah[(r + 8) * LDA2 + tr];
            ah[mi][2] = Ah[r * LDA2 + tr + 4];
            ah[mi][3] = Ah[(r + 8) * LDA2 + tr + 4];
            al[mi][0] = Al[r * LDA2 + tr];
            al[mi][1] = Al[(r + 8) * LDA2 + tr];
            al[mi][2] = Al[r * LDA2 + tr + 4];
            al[mi][3] = Al[(r + 8) * LDA2 + tr + 4];
        }
        uint32_t bh[8][2], bl[8][2];
#pragma unroll
        for (int ni = 0; ni < 8; ni++) {
            int n = ni * 8 + tq;
            if (BT) {
                bh[ni][0] = Bh[n * LDBT2 + tr];
                bh[ni][1] = Bh[n * LDBT2 + tr + 4];
                bl[ni][0] = Bl[n * LDBT2 + tr];
                bl[ni][1] = Bl[n * LDBT2 + tr + 4];
            } else {
                bh[ni][0] = Bh[tr * LDBN2 + n];
                bh[ni][1] = Bh[(tr + 4) * LDBN2 + n];
                bl[ni][0] = Bl[tr * LDBN2 + n];
                bl[ni][1] = Bl[(tr + 4) * LDBN2 + n];
            }
        }
#pragma unroll
        for (int mi = 0; mi < 2; mi++)
#pragma unroll
            for (int ni = 0; ni < 8; ni++) {
                mma16(d0[mi][ni], ah[mi], bh[ni]);   // hh
                mma16(d1[mi][ni], ah[mi], bl[ni]);   // h * lo'
                mma16(d1[mi][ni], al[mi], bh[ni]);   // lo' * h
            }
    }

    // write partial tile: D = d0 + d1 * 2^-12
#pragma unroll
    for (int mi = 0; mi < 2; mi++)
#pragma unroll
        for (int ni = 0; ni < 8; ni++)
#pragma unroll
            for (int hf = 0; hf < 2; hf++) {
                int row = bm + wid * 32 + mi * 16 + tq + hf * 8;
                int col = bn + ni * 8 + tr * 2;
                float px = d0[mi][ni][hf * 2] + d1[mi][ni][hf * 2] * INV4096;
                float py = d0[mi][ni][hf * 2 + 1] + d1[mi][ni][hf * 2 + 1] * INV4096;
                *(float2*)&dst[(size_t)row * NF + col] = make_float2(px, py);
            }
}

// ---------------------------------------------------------------------------
// Fused phase GEMM kernels (1-D grid of uniform-duration CTAs)
// m-tiles per GEMM = 2 (BATCH/128). n-tiles: mode0 64, mode1 128, mode2 32,
// mode3 64.
// upd: mode2 (4p x 32n x 2m = 256) + mode3 (8 x 64 x 2 = 1024) = 1280
// err: mode0 (2p x 64n x 2m = 256) + mode1 (4 x 128 x 2 = 1024) = 1280
// ---------------------------------------------------------------------------
__global__ __launch_bounds__(128, 3)
void upd_gemm() {
    int b = blockIdx.x;
    if (b < 256) {
        int part = b >> 6, t = b & 63;
        gemm_body<2>(t & 31, t >> 5, part);
    } else {
        int b2 = b - 256;
        int part = b2 >> 7, t = b2 & 127;
        gemm_body<3>(t & 63, t >> 6, part);
    }
}
__global__ __launch_bounds__(128, 3)
void err_gemm(int boff) {
    int b = blockIdx.x + boff;
    if (b < 256) {
        int part = b >> 7, t = b & 127;
        gemm_body<0>(t & 63, t >> 6, part);
    } else {
        int b2 = b - 256;
        int part = b2 >> 8, t = b2 & 255;
        gemm_body<1>(t & 127, t >> 7, part);
    }
}

// ---------------------------------------------------------------------------
// Epilogue kernels (elementwise, float4; also emit packed fp16 splits)
// ---------------------------------------------------------------------------
__device__ __forceinline__ void block_loss(float lsum, int loss_idx) {
    __shared__ float wred[8];
    int tid = threadIdx.x;
#pragma unroll
    for (int o = 16; o > 0; o >>= 1)
        lsum += __shfl_down_sync(0xffffffffu, lsum, o);
    if ((tid & 31) == 0) wred[tid >> 5] = lsum;
    __syncthreads();
    if (tid == 0 && loss_idx >= 0) {
        float s = 0.f;
#pragma unroll
        for (int w = 0; w < 8; w++) s += wred[w];
        atomicAdd(&g_loss[loss_idx], (double)s);
    }
}

// grid 1536 x 256 : v0 update (131072 f4) then v1 update (262144 f4)
__global__ __launch_bounds__(256)
void upd_epi(const float* __restrict__ memory, const float* __restrict__ lr_p,
             int loss_idx) {
    int i = blockIdx.x * blockDim.x + threadIdx.x;
    float lr = *lr_p;
    float lsum = 0.f;
    if (i < BATCH * N0 / 4) {
        float4 acc[4];
#pragma unroll
        for (int p = 0; p < 4; p++) acc[p] = ((const float4*)sP0[p])[i];
        float4 v4 = ((const float4*)g_v0)[i];
        float4 e4 = ((const float4*)g_e0)[i];
        float4 t4 = ((const float4*)g_t0)[i];
        float4 m4 = *(const float4*)&memory[(i * 4) & (N0 - 1)];
        float* v = &v4.x; float* e = &e4.x; float* t = &t4.x; float* m = &m4.x;
        float4 nv4, nt4, ne4;
        float* nv = &nv4.x; float* nt = &nt4.x; float* ne = &ne4.x;
#pragma unroll
        for (int c = 0; c < 4; c++) {
            float g = ((&acc[0].x)[c] + (&acc[1].x)[c]) +
                      ((&acc[2].x)[c] + (&acc[3].x)[c]);
            float sg = (v[c] > 0.f) ? 1.f : ((v[c] < 0.f) ? -1.f : 0.f);
            float x = fmaxf(v[c] + lr * (-e[c] - LAMB * sg + (1.f - t[c] * t[c]) * g), 0.f);
            nv[c] = x;
            nt[c] = tanhf(x);
            float er = x - m[c];
            ne[c] = er;
            lsum += er * er;
        }
        ((float4*)g_v0)[i] = nv4;
        ((float4*)g_t0)[i] = nt4;
        ((float4*)g_e0)[i] = ne4;
        uint2 hi, lo;
        split4(nt4, hi, lo);
        g_t0ph[i] = hi;
        g_t0pl[i] = lo;
    } else {
        int j = i - BATCH * N0 / 4;
        float4 acc[8];
#pragma unroll
        for (int p = 0; p < 8; p++) acc[p] = ((const float4*)sP1[p])[j];
        float4 v4 = ((const float4*)g_v1)[j];
        float4 e4 = ((const float4*)g_e1)[j];
        float4 t4 = ((const float4*)g_t1)[j];
        float* v = &v4.x; float* e = &e4.x; float* t = &t4.x;
        float4 nv4, nt4;
        float* nv = &nv4.x; float* nt = &nt4.x;
#pragma unroll
        for (int c = 0; c < 4; c++) {
            float g = (((&acc[0].x)[c] + (&acc[1].x)[c]) +
                       ((&acc[2].x)[c] + (&acc[3].x)[c])) +
                      (((&acc[4].x)[c] + (&acc[5].x)[c]) +
                       ((&acc[6].x)[c] + (&acc[7].x)[c]));
            float x = fmaxf(v[c] + lr * (-e[c] + (1.f - t[c] * t[c]) * g), 0.f);
            nv[c] = x;
            nt[c] = tanhf(x);
        }
        ((float4*)g_v1)[j] = nv4;
        ((float4*)g_t1)[j] = nt4;
        uint2 hi, lo;
        split4(nt4, hi, lo);
        g_t1ph[j] = hi;
        g_t1pl[j] = lo;
    }
    block_loss(lsum, loss_idx);
}

// grid 3072 x 256 : e1 (262144 f4, skipped when mode=1) then e2 (524288 f4)
__global__ __launch_bounds__(256)
void err_epi(const float* __restrict__ inp, int loss_idx, int mode) {
    int i = blockIdx.x * blockDim.x + threadIdx.x;
    float lsum = 0.f;
    if (i < BATCH * N1 / 4) {
        if (mode == 0) {
            float4 q0 = ((const float4*)sQ1[0])[i];
            float4 q1 = ((const float4*)sQ1[1])[i];
            float4 v = ((const float4*)g_v1)[i];
            float4 e = make_float4(v.x - (q0.x + q1.x), v.y - (q0.y + q1.y),
                                   v.z - (q0.z + q1.z), v.w - (q0.w + q1.w));
            ((float4*)g_e1)[i] = e;
            uint2 hi, lo;
            split4(e, hi, lo);
            g_e1ph[i] = hi;
            g_e1pl[i] = lo;
            lsum = e.x * e.x + e.y * e.y + e.z * e.z + e.w * e.w;
        }
    } else {
        int j = i - BATCH * N1 / 4;
        float4 q0 = ((const float4*)sQ2[0])[j];
        float4 q1 = ((const float4*)sQ2[1])[j];
        float4 q2 = ((const float4*)sQ2[2])[j];
        float4 q3 = ((const float4*)sQ2[3])[j];
        float4 x = ((const float4*)inp)[j];
        float4 e = make_float4(x.x - ((q0.x + q1.x) + (q2.x + q3.x)),
                               x.y - ((q0.y + q1.y) + (q2.y + q3.y)),
                               x.z - ((q0.z + q1.z) + (q2.z + q3.z)),
                               x.w - ((q0.w + q1.w) + (q2.w + q3.w)));
        uint2 hi, lo;
        split4(e, hi, lo);
        g_e2ph[j] = hi;
        g_e2pl[j] = lo;
        lsum = e.x * e.x + e.y * e.y + e.z * e.z + e.w * e.w;
    }
    block_loss(lsum, loss_idx);
}

// grid 1024 x 256 : v1 = sum(sQ1), t1 = tanh(v1) (+ t1 splits)
__global__ __launch_bounds__(256)
void fwd_epi() {
    int i = blockIdx.x * blockDim.x + threadIdx.x;
    float4 q0 = ((const float4*)sQ1[0])[i];
    float4 q1 = ((const float4*)sQ1[1])[i];
    float4 q = make_float4(q0.x + q1.x, q0.y + q1.y, q0.z + q1.z, q0.w + q1.w);
    ((float4*)g_v1)[i] = q;
    float4 t = make_float4(tanhf(q.x), tanhf(q.y), tanhf(q.z), tanhf(q.w));
    ((float4*)g_t1)[i] = t;
    uint2 hi, lo;
    split4(t, hi, lo);
    g_t1ph[i] = hi;
    g_t1pl[i] = lo;
}

__global__ void finalize_kernel(float* __restrict__ out, int n) {
    int i = threadIdx.x;
    if (i < n) out[i] = (float)(g_loss[i] * (100.0 / (double)BATCH));
}

// ---------------------------------------------------------------------------
// Launch (graph-capturable)
// Inputs: batch_inp, W0, W1, memory, n_iters, inf_lr
// ---------------------------------------------------------------------------
extern "C" void kernel_launch(void* const* d_in, const int* in_sizes, int n_in,
                              void* d_out, int out_size) {
    const float* batch_inp = (const float*)d_in[0];
    const float* W0 = (const float*)d_in[1];
    const float* W1 = (const float*)d_in[2];
    const float* memory = (const float*)d_in[3];
    const float* inf_lr = (const float*)d_in[5];

    int n_iters = out_size;
    if (n_iters > MAX_ITERS) n_iters = MAX_ITERS;

    cudaFuncSetAttribute(upd_gemm, cudaFuncAttributeMaxDynamicSharedMemorySize, SMEM_BYTES);
    cudaFuncSetAttribute(err_gemm, cudaFuncAttributeMaxDynamicSharedMemorySize, SMEM_BYTES);

    // weight splits (pure function of inputs; recomputed each call)
    split_w_bt<<<2048, 256>>>(W0, 0, N1 * N0 / 2);
    split_w_bt<<<4096, 256>>>(W1, 1, N2 * N1 / 2);
    split_w_nn<<<2048, 256>>>(W0, 0);
    split_w_nn<<<4096, 256>>>(W1, 1);
    init_state_k<<<512, 256>>>(memory);

    // init: v1 = t0@W0^T, t1 = tanh(v1); e1 stays exactly 0; e2 = inp - t1@W1^T
    err_gemm<<<256, 128, SMEM_BYTES>>>(0);      // mode 0 -> sQ1[0..1]
    fwd_epi<<<1024, 256>>>();
    err_gemm<<<1024, 128, SMEM_BYTES>>>(256);   // mode 1 -> sQ2[0..3]
    err_epi<<<3072, 256>>>(batch_inp, -1, 1);   // e2 only, no loss

    for (int it = 0; it < n_iters; it++) {
        upd_gemm<<<1280, 128, SMEM_BYTES>>>();
        upd_epi<<<1536, 256>>>(memory, inf_lr, it);
        err_gemm<<<1280, 128, SMEM_BYTES>>>(0);
        err_epi<<<3072, 256>>>(batch_inp, it, 0);
    }

    finalize_kernel<<<1, MAX_ITERS>>>((float*)d_out, n_iters);
}